// round 11
// baseline (speedup 1.0000x reference)
#include <cuda_runtime.h>
#include <cstdint>

#define Bc 2
#define Nc 4096
#define Tc 512
#define CAP 64

// ---------------- scratch (static device globals; no allocation) ----------------
__device__ float  g_s2c[Bc * Tc * 128];                 // s_to_c
__device__ int    g_tok[Bc * Nc];                       // token index per atom
__device__ float  g_cq[Bc * Nc * 16];                   // relu(c) @ W_cq.T
__device__ float  g_ck[Bc * Nc * 16];                   // relu(c) @ W_ck.T
__device__ float  g_z2pc[(size_t)Bc * Tc * CAP * 16];   // compact z2p window (4 MB)
__device__ int    g_lo[Bc * Tc];                        // key-token window start per (b,tq)
__device__ int    g_amin[Bc * Tc];
__device__ int    g_amax[Bc * Tc];
__device__ int    g_anyovf;                             // any (b,tq) window exceeded CAP?
__device__ float2 g_WfP2[196 * 128];                    // (w[2f2][ch], w[2f2+1][ch]) non-dup
__device__ float  g_Ws2cT[384 * 128];
__device__ float  g_gw[16 * 128];                       // W_z2p * ln_z_g (folded)
__device__ float  g_gsum[16];
__device__ float  g_bw[16];

// ---------------- f32x2 / bf16 helpers ----------------
__device__ __forceinline__ void fma2(unsigned long long& acc, unsigned long long a, unsigned long long b) {
    asm("fma.rn.f32x2 %0, %1, %2, %0;" : "+l"(acc) : "l"(a), "l"(b));
}
__device__ __forceinline__ unsigned long long add2(unsigned long long a, unsigned long long b) {
    unsigned long long r;
    asm("add.rn.f32x2 %0, %1, %2;" : "=l"(r) : "l"(a), "l"(b));
    return r;
}
__device__ __forceinline__ unsigned long long dup2(float w) {
    unsigned long long r;
    asm("mov.b64 %0, {%1,%1};" : "=l"(r) : "f"(w));
    return r;
}
__device__ __forceinline__ float lo32(unsigned long long v) { return __uint_as_float((unsigned)(v & 0xffffffffu)); }
__device__ __forceinline__ float hi32(unsigned long long v) { return __uint_as_float((unsigned)(v >> 32)); }
__device__ __forceinline__ unsigned pkbf(float lo, float hi) {
    unsigned r;
    asm("cvt.rn.bf16x2.f32 %0, %1, %2;" : "=r"(r) : "f"(hi), "f"(lo));
    return r;
}
__device__ __forceinline__ void mma16816(float* d, unsigned a0, unsigned a1, unsigned a2, unsigned a3,
                                         unsigned b0, unsigned b1) {
    asm("mma.sync.aligned.m16n8k16.row.col.f32.bf16.bf16.f32 "
        "{%0,%1,%2,%3}, {%4,%5,%6,%7}, {%8,%9}, {%10,%11,%12,%13};"
        : "=f"(d[0]), "=f"(d[1]), "=f"(d[2]), "=f"(d[3])
        : "r"(a0), "r"(a1), "r"(a2), "r"(a3), "r"(b0), "r"(b1),
          "f"(0.f), "f"(0.f), "f"(0.f), "f"(0.f));
}

// ---------------- prep: weight tables + layernorm fold + range/flag init ----------------
__global__ void prep_kernel(const float* __restrict__ W_feat, const float* __restrict__ W_s2c,
                            const float* __restrict__ W_z2p, const float* __restrict__ ln_z_g,
                            const float* __restrict__ ln_z_b) {
    int t = blockIdx.x * blockDim.x + threadIdx.x;
    int nt = gridDim.x * blockDim.x;
    for (int i = t; i < 196 * 128; i += nt) {
        int f2 = i >> 7, ch = i & 127;
        int fi0 = 2 * f2, fi1 = fi0 + 1;
        float w0 = (fi0 < 389) ? W_feat[ch * 389 + fi0] : 0.f;
        float w1 = (fi1 < 389) ? W_feat[ch * 389 + fi1] : 0.f;
        g_WfP2[i] = make_float2(w0, w1);
    }
    for (int i = t; i < 384 * 128; i += nt) {
        int ch = i / 384, f = i % 384;
        g_Ws2cT[f * 128 + ch] = W_s2c[i];
    }
    for (int i = t; i < 16 * 128; i += nt) {
        g_gw[i] = W_z2p[i] * ln_z_g[i & 127];
    }
    for (int i = t; i < Bc * Tc; i += nt) { g_amin[i] = Nc; g_amax[i] = -1; }
    if (t == 0) g_anyovf = 0;
    if (t < 16) {
        float gs = 0.f, bw = 0.f;
        for (int f = 0; f < 128; f++) {
            gs += W_z2p[t * 128 + f] * ln_z_g[f];
            bw += W_z2p[t * 128 + f] * ln_z_b[f];
        }
        g_gsum[t] = gs;
        g_bw[t] = bw;
    }
}

// ---- fused: blocks [0,1024): token argmax + atom-range; blocks [1024,1536): s2c 2 rows ----
__global__ void __launch_bounds__(256) tok_s2c_kernel(
        const float* __restrict__ a2t, const float* __restrict__ s_trunk,
        const float* __restrict__ g, const float* __restrict__ bta) {
    __shared__ __align__(16) float xs2[2][384];
    __shared__ float red2[2][8];
    int tid = threadIdx.x;

    if (blockIdx.x < 1024) {
        // ---- tok: warp per atom ----
        int warp = blockIdx.x * 8 + (tid >> 5);
        int lane = tid & 31;
        const float4* row = (const float4*)(a2t + (size_t)warp * Tc);
        int idx = 0;
#pragma unroll
        for (int i = 0; i < 4; i++) {
            float4 v = row[lane + 32 * i];
            int base = 4 * (lane + 32 * i);
            if (v.x > 0.5f) idx = base;
            if (v.y > 0.5f) idx = base + 1;
            if (v.z > 0.5f) idx = base + 2;
            if (v.w > 0.5f) idx = base + 3;
        }
#pragma unroll
        for (int o = 16; o; o >>= 1) idx = max(idx, __shfl_xor_sync(0xffffffffu, idx, o));
        if (lane == 0) {
            g_tok[warp] = idx;
            int b = warp >> 12;
            int al = warp & (Nc - 1);
            atomicMin(&g_amin[b * Tc + idx], al);
            atomicMax(&g_amax[b * Tc + idx], al);
        }
        return;
    }

    // ---- s2c: 2 rows per block, 128 threads per row ----
    int half = tid >> 7;
    int t2 = tid & 127;
    int row = (blockIdx.x - 1024) * 2 + half;
    const float* x = s_trunk + (size_t)row * 384;
    float v0 = x[t2], v1 = x[t2 + 128], v2 = x[t2 + 256];
    float s = v0 + v1 + v2, s2 = v0 * v0 + v1 * v1 + v2 * v2;
#pragma unroll
    for (int o = 16; o; o >>= 1) {
        s += __shfl_xor_sync(0xffffffffu, s, o);
        s2 += __shfl_xor_sync(0xffffffffu, s2, o);
    }
    if ((t2 & 31) == 0) { red2[half][t2 >> 5] = s; red2[half][4 + (t2 >> 5)] = s2; }
    __syncthreads();
    s = red2[half][0] + red2[half][1] + red2[half][2] + red2[half][3];
    s2 = red2[half][4] + red2[half][5] + red2[half][6] + red2[half][7];
    float mu = s * (1.f / 384.f);
    float var = s2 * (1.f / 384.f) - mu * mu;
    float rs = rsqrtf(var + 1e-5f);
    xs2[half][t2]       = (v0 - mu) * rs * g[t2]       + bta[t2];
    xs2[half][t2 + 128] = (v1 - mu) * rs * g[t2 + 128] + bta[t2 + 128];
    xs2[half][t2 + 256] = (v2 - mu) * rs * g[t2 + 256] + bta[t2 + 256];
    __syncthreads();
    float acc = 0.f;
#pragma unroll 4
    for (int f = 0; f < 384; f++) acc += xs2[half][f] * g_Ws2cT[f * 128 + t2];
    g_s2c[(size_t)row * 128 + t2] = acc;
}

// ---- c embedding + cq/ck heads: 8 atoms/block, split-fi halves, 85 MAC/wavefront ----
__global__ void __launch_bounds__(256) c_kernel(
        const float* __restrict__ ref_pos, const float* __restrict__ ref_charge,
        const float* __restrict__ amask, const float* __restrict__ elem,
        const float* __restrict__ chars,
        const float* __restrict__ W_cq, const float* __restrict__ W_ck) {
    // phase1: fs[392][12] (8 atoms + 4 pad, rows 48B, 16B-aligned)
    // phase2 overlay: cs[8][128] at sm[0..1023]; reduction buf at sm[1024..2047];
    //                 wcs[2][16][130] at sm[1024..5183]
    __shared__ __align__(16) float sm[5200];
    __shared__ int ts[8];
    int tid = threadIdx.x;
    int abase = blockIdx.x * 8;

#pragma unroll
    for (int pass = 0; pass < 2; pass++) {
        int fi = tid + pass * 256;
        if (fi < 392) {
            float* row = sm + fi * 12;
#pragma unroll 4
            for (int a = 0; a < 8; a++) {
                int atom = abase + a;
                float v;
                if (fi < 3)        v = ref_pos[atom * 3 + fi];
                else if (fi == 3)  v = ref_charge[atom];
                else if (fi == 4)  v = amask[atom];
                else if (fi < 133) v = elem[(size_t)atom * 128 + (fi - 5)];
                else if (fi < 389) v = chars[(size_t)atom * 256 + (fi - 133)];
                else               v = 0.f;
                row[a] = v;
            }
        }
    }
    if (tid < 8) ts[tid] = g_tok[abase + tid];
    __syncthreads();

    int ch = tid & 127;
    int fih = tid >> 7;                  // 0: f2 0..97, 1: f2 98..195
    const float2* wp = (const float2*)g_WfP2 + (size_t)fih * 98 * 128 + ch;
    const char* fb = (const char*)sm + (size_t)fih * 98 * 96;
    unsigned long long acc0 = 0, acc1 = 0, acc2 = 0, acc3 = 0;
#pragma unroll 7
    for (int f2 = 0; f2 < 98; f2++) {
        float2 ww = wp[(size_t)f2 * 128];               // weights fi (.x), fi+1 (.y)
        unsigned long long w0d = dup2(ww.x);
        unsigned long long w1d = dup2(ww.y);
        const char* r0 = fb + (size_t)f2 * 96;
        ulonglong2 fa  = *(const ulonglong2*)(r0);      // atoms (0,1),(2,3) @ fi
        ulonglong2 fbv = *(const ulonglong2*)(r0 + 16); // atoms (4,5),(6,7) @ fi
        ulonglong2 fc  = *(const ulonglong2*)(r0 + 48); // @ fi+1
        ulonglong2 fd  = *(const ulonglong2*)(r0 + 64);
        fma2(acc0, fa.x, w0d);  fma2(acc1, fa.y, w0d);
        fma2(acc2, fbv.x, w0d); fma2(acc3, fbv.y, w0d);
        fma2(acc0, fc.x, w1d);  fma2(acc1, fc.y, w1d);
        fma2(acc2, fd.x, w1d);  fma2(acc3, fd.y, w1d);
    }
    __syncthreads();                      // all fs reads done

    unsigned long long* rbuf = (unsigned long long*)(sm + 1024);
    if (fih == 1) {
        rbuf[ch * 4 + 0] = acc0;
        rbuf[ch * 4 + 1] = acc1;
        rbuf[ch * 4 + 2] = acc2;
        rbuf[ch * 4 + 3] = acc3;
    }
    __syncthreads();

    float* cs = sm;                       // [8][128]
    if (fih == 0) {
        acc0 = add2(acc0, rbuf[ch * 4 + 0]);
        acc1 = add2(acc1, rbuf[ch * 4 + 1]);
        acc2 = add2(acc2, rbuf[ch * 4 + 2]);
        acc3 = add2(acc3, rbuf[ch * 4 + 3]);
        int bb = abase >> 12;
        const float* srow = g_s2c + (size_t)bb * Tc * 128 + ch;
        cs[0 * 128 + ch] = fmaxf(lo32(acc0) + srow[(size_t)ts[0] * 128], 0.f);
        cs[1 * 128 + ch] = fmaxf(hi32(acc0) + srow[(size_t)ts[1] * 128], 0.f);
        cs[2 * 128 + ch] = fmaxf(lo32(acc1) + srow[(size_t)ts[2] * 128], 0.f);
        cs[3 * 128 + ch] = fmaxf(hi32(acc1) + srow[(size_t)ts[3] * 128], 0.f);
        cs[4 * 128 + ch] = fmaxf(lo32(acc2) + srow[(size_t)ts[4] * 128], 0.f);
        cs[5 * 128 + ch] = fmaxf(hi32(acc2) + srow[(size_t)ts[5] * 128], 0.f);
        cs[6 * 128 + ch] = fmaxf(lo32(acc3) + srow[(size_t)ts[6] * 128], 0.f);
        cs[7 * 128 + ch] = fmaxf(hi32(acc3) + srow[(size_t)ts[7] * 128], 0.f);
    }
    __syncthreads();                      // rbuf consumed, cs written

    float* wcs = sm + 1024;               // [2][16][130]
    for (int idx = tid; idx < 2 * 16 * 128; idx += 256) {
        int which = idx >> 11, i = (idx >> 7) & 15, chh = idx & 127;
        wcs[(which * 16 + i) * 130 + chh] = which ? W_ck[i * 128 + chh] : W_cq[i * 128 + chh];
    }
    __syncthreads();

    int i = tid & 15, which = (tid >> 4) & 1, a = tid >> 5;    // one output per thread
    const unsigned long long* wr = (const unsigned long long*)(wcs + (which * 16 + i) * 130);
    const unsigned long long* cr = (const unsigned long long*)(cs + a * 128);
    unsigned long long s = 0;
#pragma unroll 16
    for (int t2 = 0; t2 < 64; t2++) fma2(s, cr[t2], wr[t2]);
    float* dst = which ? g_ck : g_cq;
    dst[(size_t)(abase + a) * 16 + i] = lo32(s) + hi32(s);
}

// ---------------- compact z_to_p: one block per (b,tq); computes lo + overflow flag ----
__global__ void z2pc_kernel(const float* __restrict__ z) {
    __shared__ __align__(16) float xs[64 * 132];
    __shared__ __align__(16) float gws[16 * 130];
    __shared__ float mus[64], rss[64], gsum_s[16], bw_s[16];
    __shared__ int lo_s;
    int tid = threadIdx.x;
    int bt = blockIdx.x;                 // b*Tc + tq

    if (tid == 0) {
        int lo = 0;
        int amx = g_amax[bt];
        if (amx >= 0) {
            int amn = g_amin[bt];
            int alo = 32 * (amn >> 5) - 48; if (alo < 0) alo = 0;
            int ahi = 32 * (amx >> 5) + 79; if (ahi > Nc - 1) ahi = Nc - 1;
            int bO = (bt >> 9) * Nc;
            lo = g_tok[bO + alo];
            int hi = g_tok[bO + ahi];
            if (hi - lo >= CAP) g_anyovf = 1;
        }
        g_lo[bt] = lo;
        lo_s = lo;
    }
    for (int i = tid; i < 2048; i += 256)
        gws[(i >> 7) * 130 + (i & 127)] = g_gw[i];
    if (tid < 16) { gsum_s[tid] = g_gsum[tid]; bw_s[tid] = g_bw[tid]; }
    __syncthreads();
    int lo = lo_s;

    {
        int r = tid >> 2, j = tid & 3;
        int tk = lo + r;
        if (tk > Tc - 1) tk = Tc - 1;
        const float4* src = (const float4*)(z + ((size_t)bt * Tc + tk) * 128) + j * 8;
        float4* dst = (float4*)(xs + r * 132) + j * 8;
        float s = 0.f, s2 = 0.f;
#pragma unroll
        for (int q = 0; q < 8; q++) {
            float4 t = src[q];
            dst[q] = t;
            s += (t.x + t.y) + (t.z + t.w);
            s2 += t.x * t.x + t.y * t.y + t.z * t.z + t.w * t.w;
        }
        s  += __shfl_xor_sync(0xffffffffu, s, 1);
        s2 += __shfl_xor_sync(0xffffffffu, s2, 1);
        s  += __shfl_xor_sync(0xffffffffu, s, 2);
        s2 += __shfl_xor_sync(0xffffffffu, s2, 2);
        if (j == 0) {
            float mu = s * (1.f / 128.f);
            float var = s2 * (1.f / 128.f) - mu * mu;
            mus[r] = mu;
            rss[r] = rsqrtf(var + 1e-5f);
        }
    }
    __syncthreads();

    int ch = tid & 15, rb = tid >> 4;
    const unsigned long long* wp = (const unsigned long long*)(gws + ch * 130);
    const unsigned long long* x0 = (const unsigned long long*)(xs + (rb * 4 + 0) * 132);
    const unsigned long long* x1 = (const unsigned long long*)(xs + (rb * 4 + 1) * 132);
    const unsigned long long* x2 = (const unsigned long long*)(xs + (rb * 4 + 2) * 132);
    const unsigned long long* x3 = (const unsigned long long*)(xs + (rb * 4 + 3) * 132);
    unsigned long long a0 = 0, a1 = 0, a2 = 0, a3 = 0;
#pragma unroll 16
    for (int f2 = 0; f2 < 64; f2++) {
        unsigned long long w = wp[f2];
        fma2(a0, x0[f2], w);
        fma2(a1, x1[f2], w);
        fma2(a2, x2[f2], w);
        fma2(a3, x3[f2], w);
    }
    float gs = gsum_s[ch], bw = bw_s[ch];
    float dots[4] = { lo32(a0) + hi32(a0), lo32(a1) + hi32(a1),
                      lo32(a2) + hi32(a2), lo32(a3) + hi32(a3) };
#pragma unroll
    for (int i = 0; i < 4; i++) {
        int r = rb * 4 + i;
        g_z2pc[((size_t)bt * CAP + r) * 16 + ch] = rss[r] * (dots[i] - mus[r] * gs) + bw;
    }
}

// ---------------- main: 1 position per thread; MLP via warp mma; straight-line ----
__global__ void __launch_bounds__(256) main_kernel(
        const float* __restrict__ ref_pos, const float* __restrict__ amask,
        const int* __restrict__ uid,
        const float* __restrict__ W_pos, const float* __restrict__ W_dist,
        const float* __restrict__ W_maskp,
        const float* __restrict__ W_m1, const float* __restrict__ W_m2,
        const float* __restrict__ W_m3,
        float* __restrict__ out) {
    __shared__ __align__(16) float sw[16 * 8];     // per-d packed (wpx,wpy,wpz,wdist,wmk,...)
    __shared__ unsigned stg[8 * 288];              // bf16 staging, stride 9 (conflict-free)
    __shared__ __align__(16) float res[8 * 640];   // f32 results, stride 20
    int tid = threadIdx.x;
    int lane = tid & 31, wid = tid >> 5;
    int g = lane >> 2, t = lane & 3;
    if (tid < 16) {
        sw[tid * 8 + 0] = W_pos[3 * tid];
        sw[tid * 8 + 1] = W_pos[3 * tid + 1];
        sw[tid * 8 + 2] = W_pos[3 * tid + 2];
        sw[tid * 8 + 3] = W_dist[tid];
        sw[tid * 8 + 4] = W_maskp[tid];
    }

    unsigned bf[3][4];
#pragma unroll
    for (int L = 0; L < 3; L++) {
        const float* W = (L == 0) ? W_m1 : (L == 1) ? W_m2 : W_m3;
        float2 w00 = *(const float2*)(W + g * 16 + 2 * t);
        float2 w01 = *(const float2*)(W + g * 16 + 2 * t + 8);
        float2 w10 = *(const float2*)(W + (g + 8) * 16 + 2 * t);
        float2 w11 = *(const float2*)(W + (g + 8) * 16 + 2 * t + 8);
        bf[L][0] = pkbf(w00.x, w00.y);
        bf[L][1] = pkbf(w01.x, w01.y);
        bf[L][2] = pkbf(w10.x, w10.y);
        bf[L][3] = pkbf(w11.x, w11.y);
    }
    __syncthreads();

    int gidx = blockIdx.x * 256 + tid;
    int hh = gidx & 127;
    int ww = (gidx >> 7) & 31;
    int kk = (gidx >> 12) & 127;
    int b  = gidx >> 19;
    int q = kk * 32 + ww;
    int bq = b * Nc + q;
    int key = kk * 32 + hh - 48;
    bool inr = (unsigned)key < (unsigned)Nc;
    int bk = b * Nc + (inr ? key : 0);

    float mq = amask[bq];
    float mk = inr ? amask[bk] : 0.f;
    int uq = uid[bq];
    int uk = uid[bk];
    float v = (mq != 0.f && mk != 0.f && uq == uk) ? 1.f : 0.f;

    float qx = ref_pos[bq * 3], qy = ref_pos[bq * 3 + 1], qz = ref_pos[bq * 3 + 2];
    float kx = 0.f, ky = 0.f, kz = 0.f;
    if (inr) { kx = ref_pos[bk * 3]; ky = ref_pos[bk * 3 + 1]; kz = ref_pos[bk * 3 + 2]; }
    float dx = kx - qx, dy = ky - qy, dz = kz - qz;
    float dn = 1.f / (1.f + dx * dx + dy * dy + dz * dz);

    float p[16];
#pragma unroll
    for (int d = 0; d < 16; d++) {
        float4 wv = *(const float4*)(sw + d * 8);
        float e = sw[d * 8 + 4];
        p[d] = v * (dx * wv.x + dy * wv.y + dz * wv.z + dn * wv.w + e);
    }
    {
        const float4* cq4 = (const float4*)(g_cq + (size_t)bq * 16);
#pragma unroll
        for (int i = 0; i < 4; i++) {
            float4 tt = cq4[i];
            p[4 * i] += tt.x; p[4 * i + 1] += tt.y; p[4 * i + 2] += tt.z; p[4 * i + 3] += tt.w;
        }
    }
    if (inr) {
        int tq = g_tok[bq];            // uniform per query (warp-broadcast)
        int bt = (b << 9) + tq;
        int lo = g_lo[bt];             // uniform
        int zoff = bt * CAP;
        int j = g_tok[bk] - lo;        // j >= 0 guaranteed by window construction
        if (j >= CAP) j = CAP - 1;     // overflow handled exactly by fixup_kernel
        const float4* zp4 = (const float4*)(g_z2pc + (size_t)(zoff + j) * 16);
        const float4* ck4 = (const float4*)(g_ck + (size_t)bk * 16);
#pragma unroll
        for (int i = 0; i < 4; i++) {
            float4 tt = zp4[i], u = ck4[i];
            p[4 * i]     += tt.x + u.x;
            p[4 * i + 1] += tt.y + u.y;
            p[4 * i + 2] += tt.z + u.z;
            p[4 * i + 3] += tt.w + u.w;
        }
    }

    // stage relu(p) as bf16 rows: [32 rows x 9 u32] per warp (stride 9 = conflict-free)
    unsigned* h2 = stg + wid * 288;
#pragma unroll
    for (int j2 = 0; j2 < 8; j2++)
        h2[lane * 9 + j2] = pkbf(fmaxf(p[2 * j2], 0.f), fmaxf(p[2 * j2 + 1], 0.f));
    __syncwarp();

    unsigned a0[2], a1[2], a2[2], a3[2];
#pragma unroll
    for (int tt = 0; tt < 2; tt++) {
        int rt = tt * 16;
        a0[tt] = h2[(rt + g) * 9 + t];
        a1[tt] = h2[(rt + g + 8) * 9 + t];
        a2[tt] = h2[(rt + g) * 9 + t + 4];
        a3[tt] = h2[(rt + g + 8) * 9 + t + 4];
    }
    __syncwarp();

    float* wsm = res + wid * 640;
#pragma unroll
    for (int tt = 0; tt < 2; tt++) {
        unsigned u0 = a0[tt], u1 = a1[tt], u2 = a2[tt], u3 = a3[tt];
        float dlo[4], dhi[4];
#pragma unroll
        for (int L = 0; L < 3; L++) {
            mma16816(dlo, u0, u1, u2, u3, bf[L][0], bf[L][1]);
            mma16816(dhi, u0, u1, u2, u3, bf[L][2], bf[L][3]);
            if (L < 2) {
                u0 = pkbf(fmaxf(dlo[0], 0.f), fmaxf(dlo[1], 0.f));
                u1 = pkbf(fmaxf(dlo[2], 0.f), fmaxf(dlo[3], 0.f));
                u2 = pkbf(fmaxf(dhi[0], 0.f), fmaxf(dhi[1], 0.f));
                u3 = pkbf(fmaxf(dhi[2], 0.f), fmaxf(dhi[3], 0.f));
            }
        }
        int r0 = tt * 16 + g, r1 = r0 + 8;
        *(float2*)(wsm + r0 * 20 + 2 * t)     = make_float2(dlo[0], dlo[1]);
        *(float2*)(wsm + r1 * 20 + 2 * t)     = make_float2(dlo[2], dlo[3]);
        *(float2*)(wsm + r0 * 20 + 8 + 2 * t) = make_float2(dhi[0], dhi[1]);
        *(float2*)(wsm + r1 * 20 + 8 + 2 * t) = make_float2(dhi[2], dhi[3]);
    }
    __syncwarp();

    float4* o4 = (float4*)(out + (size_t)gidx * 16);
    const float4* mrow = (const float4*)(wsm + lane * 20);
#pragma unroll
    for (int i = 0; i < 4; i++) {
        float4 mi = mrow[i];
        __stcs(o4 + i, make_float4(p[4 * i] + mi.x, p[4 * i + 1] + mi.y,
                                   p[4 * i + 2] + mi.z, p[4 * i + 3] + mi.w));
    }
}

// ---------------- fixup: exact recompute of window-overflow positions (rare) ----------
__global__ void fixup_kernel(
        const float* __restrict__ ref_pos, const float* __restrict__ amask,
        const int* __restrict__ uid, const float* __restrict__ z,
        const float* __restrict__ W_pos, const float* __restrict__ W_dist,
        const float* __restrict__ W_maskp,
        const float* __restrict__ W_m1, const float* __restrict__ W_m2,
        const float* __restrict__ W_m3,
        float* __restrict__ out) {
    if (!g_anyovf) return;
    int bt = blockIdx.x;                  // b*Tc + tq
    int amx = g_amax[bt];
    if (amx < 0) return;
    int amn = g_amin[bt];
    int b = bt >> 9;
    int alo = 32 * (amn >> 5) - 48; if (alo < 0) alo = 0;
    int ahi = 32 * (amx >> 5) + 79; if (ahi > Nc - 1) ahi = Nc - 1;
    int lo = g_tok[b * Nc + alo];
    int hi = g_tok[b * Nc + ahi];
    if (hi - lo < CAP) return;            // this tq was fully handled by main

    int hh = threadIdx.x;                 // 128 threads
    for (int q = amn; q <= amx; q++) {
        int kk = q >> 5;
        int key = kk * 32 + hh - 48;
        if ((unsigned)key >= (unsigned)Nc) continue;
        int bq = b * Nc + q;
        int bk = b * Nc + key;
        int tk2 = g_tok[bk];
        if (tk2 - lo < CAP) continue;     // main's value exact

        float mq = amask[bq], mk = amask[bk];
        float vv = (mq != 0.f && mk != 0.f && uid[bq] == uid[bk]) ? 1.f : 0.f;
        float dx = ref_pos[bk * 3] - ref_pos[bq * 3];
        float dy = ref_pos[bk * 3 + 1] - ref_pos[bq * 3 + 1];
        float dz = ref_pos[bk * 3 + 2] - ref_pos[bq * 3 + 2];
        float dn = 1.f / (1.f + dx * dx + dy * dy + dz * dz);

        const float* zrow = z + ((size_t)bt * Tc + tk2) * 128;
        float s = 0.f, s2 = 0.f;
        for (int f = 0; f < 128; f++) { float x = zrow[f]; s += x; s2 += x * x; }
        float mu = s * (1.f / 128.f);
        float rs = rsqrtf(s2 * (1.f / 128.f) - mu * mu + 1e-5f);

        float p[16];
        for (int d = 0; d < 16; d++) {
            float dot = 0.f;
            for (int f = 0; f < 128; f++) dot += zrow[f] * g_gw[d * 128 + f];
            float zc = rs * (dot - mu * g_gsum[d]) + g_bw[d];
            p[d] = vv * (dx * W_pos[3 * d] + dy * W_pos[3 * d + 1] + dz * W_pos[3 * d + 2]
                         + dn * W_dist[d] + W_maskp[d])
                   + g_cq[(size_t)bq * 16 + d] + g_ck[(size_t)bk * 16 + d] + zc;
        }
        float r0[16], r1[16], r2[16];
        for (int i = 0; i < 16; i++) {
            float a = 0.f;
            for (int j = 0; j < 16; j++) a += fmaxf(p[j], 0.f) * W_m1[i * 16 + j];
            r0[i] = a;
        }
        for (int i = 0; i < 16; i++) {
            float a = 0.f;
            for (int j = 0; j < 16; j++) a += fmaxf(r0[j], 0.f) * W_m2[i * 16 + j];
            r1[i] = a;
        }
        for (int i = 0; i < 16; i++) {
            float a = 0.f;
            for (int j = 0; j < 16; j++) a += fmaxf(r1[j], 0.f) * W_m3[i * 16 + j];
            r2[i] = a;
        }
        size_t gidx = ((size_t)b << 19) | ((size_t)kk << 12) | ((size_t)(q & 31) << 7) | hh;
        float* o = out + gidx * 16;
        for (int i = 0; i < 16; i++) o[i] = p[i] + r2[i];
    }
}

// ---------------- launch ----------------
extern "C" void kernel_launch(void* const* d_in, const int* in_sizes, int n_in,
                              void* d_out, int out_size) {
    const float* ref_pos             = (const float*)d_in[0];
    const float* ref_charge          = (const float*)d_in[1];
    const float* atom_pad_mask       = (const float*)d_in[2];
    const float* ref_element         = (const float*)d_in[3];
    const float* ref_atom_name_chars = (const float*)d_in[4];
    const int*   ref_space_uid       = (const int*)  d_in[5];
    const float* atom_to_token       = (const float*)d_in[6];
    const float* s_trunk             = (const float*)d_in[7];
    const float* z                   = (const float*)d_in[8];
    const float* W_feat              = (const float*)d_in[9];
    const float* W_pos               = (const float*)d_in[10];
    const float* W_dist              = (const float*)d_in[11];
    const float* W_maskp             = (const float*)d_in[12];
    const float* ln_s_g              = (const float*)d_in[13];
    const float* ln_s_b              = (const float*)d_in[14];
    const float* W_s2c               = (const float*)d_in[15];
    const float* ln_z_g              = (const float*)d_in[16];
    const float* ln_z_b              = (const float*)d_in[17];
    const float* W_z2p               = (const float*)d_in[18];
    const float* W_cq                = (const float*)d_in[19];
    const float* W_ck                = (const float*)d_in[20];
    const float* W_m1                = (const float*)d_in[21];
    const float* W_m2                = (const float*)d_in[22];
    const float* W_m3                = (const float*)d_in[23];
    float* out = (float*)d_out;

    prep_kernel<<<64, 256>>>(W_feat, W_s2c, W_z2p, ln_z_g, ln_z_b);
    tok_s2c_kernel<<<1536, 256>>>(atom_to_token, s_trunk, ln_s_g, ln_s_b);
    c_kernel<<<(Bc * Nc) / 8, 256>>>(ref_pos, ref_charge, atom_pad_mask,
                                     ref_element, ref_atom_name_chars, W_cq, W_ck);
    z2pc_kernel<<<Bc * Tc, 256>>>(z);
    main_kernel<<<(Bc * 128 * 32 * 128) / 256, 256>>>(ref_pos, atom_pad_mask, ref_space_uid,
                                                      W_pos, W_dist, W_maskp,
                                                      W_m1, W_m2, W_m3, out);
    fixup_kernel<<<Bc * Tc, 128>>>(ref_pos, atom_pad_mask, ref_space_uid, z,
                                   W_pos, W_dist, W_maskp, W_m1, W_m2, W_m3, out);
}

// round 12
// speedup vs baseline: 1.0820x; 1.0820x over previous
#include <cuda_runtime.h>
#include <cstdint>

#define Bc 2
#define Nc 4096
#define Tc 512
#define CAP 64

// ---------------- scratch (static device globals; no allocation) ----------------
__device__ float  g_s2c[Bc * Tc * 128];                 // s_to_c
__device__ int    g_tok[Bc * Nc];                       // token index per atom
__device__ float  g_cq[Bc * Nc * 16];                   // relu(c) @ W_cq.T
__device__ float  g_ck[Bc * Nc * 16];                   // relu(c) @ W_ck.T
__device__ float  g_z2pc[(size_t)Bc * Tc * CAP * 16];   // compact z2p window (4 MB)
__device__ int    g_lo[Bc * Tc];                        // key-token window start per (b,tq)
__device__ int    g_amin[Bc * Tc];
__device__ int    g_amax[Bc * Tc];
__device__ int    g_anyovf;                             // any (b,tq) window exceeded CAP?
__device__ float2 g_WfP2[196 * 128];                    // (w[2f2][ch], w[2f2+1][ch]) non-dup
__device__ float  g_Ws2cT[384 * 128];
__device__ float  g_gw[16 * 128];                       // W_z2p * ln_z_g (folded)
__device__ float  g_gsum[16];
__device__ float  g_bw[16];

// ---------------- f32x2 / bf16 helpers ----------------
__device__ __forceinline__ void fma2(unsigned long long& acc, unsigned long long a, unsigned long long b) {
    asm("fma.rn.f32x2 %0, %1, %2, %0;" : "+l"(acc) : "l"(a), "l"(b));
}
__device__ __forceinline__ unsigned long long dup2(float w) {
    unsigned long long r;
    asm("mov.b64 %0, {%1,%1};" : "=l"(r) : "f"(w));
    return r;
}
__device__ __forceinline__ float lo32(unsigned long long v) { return __uint_as_float((unsigned)(v & 0xffffffffu)); }
__device__ __forceinline__ float hi32(unsigned long long v) { return __uint_as_float((unsigned)(v >> 32)); }
__device__ __forceinline__ unsigned pkbf(float lo, float hi) {
    unsigned r;
    asm("cvt.rn.bf16x2.f32 %0, %1, %2;" : "=r"(r) : "f"(hi), "f"(lo));
    return r;
}
__device__ __forceinline__ void mma16816(float* d, unsigned a0, unsigned a1, unsigned a2, unsigned a3,
                                         unsigned b0, unsigned b1) {
    asm("mma.sync.aligned.m16n8k16.row.col.f32.bf16.bf16.f32 "
        "{%0,%1,%2,%3}, {%4,%5,%6,%7}, {%8,%9}, {%10,%11,%12,%13};"
        : "=f"(d[0]), "=f"(d[1]), "=f"(d[2]), "=f"(d[3])
        : "r"(a0), "r"(a1), "r"(a2), "r"(a3), "r"(b0), "r"(b1),
          "f"(0.f), "f"(0.f), "f"(0.f), "f"(0.f));
}

// ---------------- prep: weight tables + layernorm fold + range/flag init ----------------
__global__ void prep_kernel(const float* __restrict__ W_feat, const float* __restrict__ W_s2c,
                            const float* __restrict__ W_z2p, const float* __restrict__ ln_z_g,
                            const float* __restrict__ ln_z_b) {
    int t = blockIdx.x * blockDim.x + threadIdx.x;
    int nt = gridDim.x * blockDim.x;
    for (int i = t; i < 196 * 128; i += nt) {
        int f2 = i >> 7, ch = i & 127;
        int fi0 = 2 * f2, fi1 = fi0 + 1;
        float w0 = (fi0 < 389) ? W_feat[ch * 389 + fi0] : 0.f;
        float w1 = (fi1 < 389) ? W_feat[ch * 389 + fi1] : 0.f;
        g_WfP2[i] = make_float2(w0, w1);
    }
    for (int i = t; i < 384 * 128; i += nt) {
        int ch = i / 384, f = i % 384;
        g_Ws2cT[f * 128 + ch] = W_s2c[i];
    }
    for (int i = t; i < 16 * 128; i += nt) {
        g_gw[i] = W_z2p[i] * ln_z_g[i & 127];
    }
    for (int i = t; i < Bc * Tc; i += nt) { g_amin[i] = Nc; g_amax[i] = -1; }
    if (t == 0) g_anyovf = 0;
    if (t < 16) {
        float gs = 0.f, bw = 0.f;
        for (int f = 0; f < 128; f++) {
            gs += W_z2p[t * 128 + f] * ln_z_g[f];
            bw += W_z2p[t * 128 + f] * ln_z_b[f];
        }
        g_gsum[t] = gs;
        g_bw[t] = bw;
    }
}

// ---- fused: blocks [0,1024): token argmax + atom-range; blocks [1024,1536): s2c 2 rows ----
__global__ void __launch_bounds__(256) tok_s2c_kernel(
        const float* __restrict__ a2t, const float* __restrict__ s_trunk,
        const float* __restrict__ g, const float* __restrict__ bta) {
    __shared__ __align__(16) float xs2[2][384];
    __shared__ float red2[2][8];
    int tid = threadIdx.x;

    if (blockIdx.x < 1024) {
        int warp = blockIdx.x * 8 + (tid >> 5);
        int lane = tid & 31;
        const float4* row = (const float4*)(a2t + (size_t)warp * Tc);
        int idx = 0;
#pragma unroll
        for (int i = 0; i < 4; i++) {
            float4 v = row[lane + 32 * i];
            int base = 4 * (lane + 32 * i);
            if (v.x > 0.5f) idx = base;
            if (v.y > 0.5f) idx = base + 1;
            if (v.z > 0.5f) idx = base + 2;
            if (v.w > 0.5f) idx = base + 3;
        }
#pragma unroll
        for (int o = 16; o; o >>= 1) idx = max(idx, __shfl_xor_sync(0xffffffffu, idx, o));
        if (lane == 0) {
            g_tok[warp] = idx;
            int b = warp >> 12;
            int al = warp & (Nc - 1);
            atomicMin(&g_amin[b * Tc + idx], al);
            atomicMax(&g_amax[b * Tc + idx], al);
        }
        return;
    }

    int half = tid >> 7;
    int t2 = tid & 127;
    int row = (blockIdx.x - 1024) * 2 + half;
    const float* x = s_trunk + (size_t)row * 384;
    float v0 = x[t2], v1 = x[t2 + 128], v2 = x[t2 + 256];
    float s = v0 + v1 + v2, s2 = v0 * v0 + v1 * v1 + v2 * v2;
#pragma unroll
    for (int o = 16; o; o >>= 1) {
        s += __shfl_xor_sync(0xffffffffu, s, o);
        s2 += __shfl_xor_sync(0xffffffffu, s2, o);
    }
    if ((t2 & 31) == 0) { red2[half][t2 >> 5] = s; red2[half][4 + (t2 >> 5)] = s2; }
    __syncthreads();
    s = red2[half][0] + red2[half][1] + red2[half][2] + red2[half][3];
    s2 = red2[half][4] + red2[half][5] + red2[half][6] + red2[half][7];
    float mu = s * (1.f / 384.f);
    float var = s2 * (1.f / 384.f) - mu * mu;
    float rs = rsqrtf(var + 1e-5f);
    xs2[half][t2]       = (v0 - mu) * rs * g[t2]       + bta[t2];
    xs2[half][t2 + 128] = (v1 - mu) * rs * g[t2 + 128] + bta[t2 + 128];
    xs2[half][t2 + 256] = (v2 - mu) * rs * g[t2 + 256] + bta[t2 + 256];
    __syncthreads();
    float acc = 0.f;
#pragma unroll 4
    for (int f = 0; f < 384; f++) acc += xs2[half][f] * g_Ws2cT[f * 128 + t2];
    g_s2c[(size_t)row * 128 + t2] = acc;
}

// ---- c embedding + cq/ck heads: 8 atoms/block (grid 1024), LDG.64 weights + reg-dup ----
// (R8/R10-measured winner: 52.5us, occ ~80%)
__global__ void __launch_bounds__(256) c_kernel(
        const float* __restrict__ ref_pos, const float* __restrict__ ref_charge,
        const float* __restrict__ amask, const float* __restrict__ elem,
        const float* __restrict__ chars,
        const float* __restrict__ W_cq, const float* __restrict__ W_ck) {
    __shared__ __align__(16) float sm[5200];
    __shared__ int ts[8];
    int tid = threadIdx.x;
    int abase = blockIdx.x * 8;

#pragma unroll
    for (int pass = 0; pass < 2; pass++) {
        int fi = tid + pass * 256;
        if (fi < 392) {
            float* row = sm + fi * 12;
#pragma unroll 4
            for (int a = 0; a < 8; a++) {
                int atom = abase + a;
                float v;
                if (fi < 3)        v = ref_pos[atom * 3 + fi];
                else if (fi == 3)  v = ref_charge[atom];
                else if (fi == 4)  v = amask[atom];
                else if (fi < 133) v = elem[(size_t)atom * 128 + (fi - 5)];
                else if (fi < 389) v = chars[(size_t)atom * 256 + (fi - 133)];
                else               v = 0.f;
                row[a] = v;
            }
        }
    }
    if (tid < 8) ts[tid] = g_tok[abase + tid];
    __syncthreads();

    int ch = tid & 127;
    int half = tid >> 7;                   // 0: atoms 0..3, 1: atoms 4..7
    const float2* wp = (const float2*)g_WfP2 + ch;
    const char* fb = (const char*)sm + half * 16;
    unsigned long long acc0 = 0, acc1 = 0;
#pragma unroll 8
    for (int f2 = 0; f2 < 196; f2++) {
        float2 ww = wp[(size_t)f2 * 128];
        unsigned long long w0d = dup2(ww.x);
        unsigned long long w1d = dup2(ww.y);
        const char* r0 = fb + (size_t)f2 * 96;
        ulonglong2 fa = *(const ulonglong2*)(r0);
        ulonglong2 fc = *(const ulonglong2*)(r0 + 48);
        fma2(acc0, fa.x, w0d); fma2(acc1, fa.y, w0d);
        fma2(acc0, fc.x, w1d); fma2(acc1, fc.y, w1d);
    }

    int bb = abase >> 12;
    const float* srow = g_s2c + (size_t)bb * Tc * 128 + ch;
    int a0 = half * 4;
    float cv0 = fmaxf(lo32(acc0) + srow[(size_t)ts[a0]     * 128], 0.f);
    float cv1 = fmaxf(hi32(acc0) + srow[(size_t)ts[a0 + 1] * 128], 0.f);
    float cv2 = fmaxf(lo32(acc1) + srow[(size_t)ts[a0 + 2] * 128], 0.f);
    float cv3 = fmaxf(hi32(acc1) + srow[(size_t)ts[a0 + 3] * 128], 0.f);
    __syncthreads();

    float* cs  = sm;                        // [8][128]
    float* wcs = sm + 1024;                 // [2][16][130]
    cs[(a0 + 0) * 128 + ch] = cv0;
    cs[(a0 + 1) * 128 + ch] = cv1;
    cs[(a0 + 2) * 128 + ch] = cv2;
    cs[(a0 + 3) * 128 + ch] = cv3;
    for (int idx = tid; idx < 2 * 16 * 128; idx += 256) {
        int which = idx >> 11, i = (idx >> 7) & 15, chh = idx & 127;
        wcs[(which * 16 + i) * 130 + chh] = which ? W_ck[i * 128 + chh] : W_cq[i * 128 + chh];
    }
    __syncthreads();

    int i = tid & 15, which = (tid >> 4) & 1, a = tid >> 5;
    const unsigned long long* wr = (const unsigned long long*)(wcs + (which * 16 + i) * 130);
    const unsigned long long* cr = (const unsigned long long*)(cs + a * 128);
    unsigned long long s = 0;
#pragma unroll 16
    for (int t2 = 0; t2 < 64; t2++) fma2(s, cr[t2], wr[t2]);
    float* dst = which ? g_ck : g_cq;
    dst[(size_t)(abase + a) * 16 + i] = lo32(s) + hi32(s);
}

// ---- compact z_to_p: 2 blocks per (b,tq), 32 rows each (26KB smem -> 8 blocks/SM) ----
__global__ void __launch_bounds__(256) z2pc_kernel(const float* __restrict__ z) {
    __shared__ __align__(16) float xs[32 * 132];
    __shared__ __align__(16) float gws[16 * 130];
    __shared__ float mus[32], rss[32], gsum_s[16], bw_s[16];
    __shared__ int lo_s;
    int tid = threadIdx.x;
    int bt = blockIdx.x >> 1;            // b*Tc + tq
    int half = blockIdx.x & 1;           // rows [half*32, half*32+32)

    if (tid == 0) {
        int lo = 0;
        int amx = g_amax[bt];
        if (amx >= 0) {
            int amn = g_amin[bt];
            int alo = 32 * (amn >> 5) - 48; if (alo < 0) alo = 0;
            int ahi = 32 * (amx >> 5) + 79; if (ahi > Nc - 1) ahi = Nc - 1;
            int bO = (bt >> 9) * Nc;
            lo = g_tok[bO + alo];
            if (half == 0) {
                int hi = g_tok[bO + ahi];
                g_lo[bt] = lo;
                if (hi - lo >= CAP) g_anyovf = 1;
            }
        } else if (half == 0) {
            g_lo[bt] = 0;
        }
        lo_s = lo;
    }
    for (int i = tid; i < 2048; i += 256)
        gws[(i >> 7) * 130 + (i & 127)] = g_gw[i];
    if (tid < 16) { gsum_s[tid] = g_gsum[tid]; bw_s[tid] = g_bw[tid]; }
    __syncthreads();
    int lo = lo_s;

    {   // 8 threads per row, each loads 16 floats (4x float4)
        int r = tid >> 3, j = tid & 7;
        int tk = lo + half * 32 + r;
        if (tk > Tc - 1) tk = Tc - 1;
        const float4* src = (const float4*)(z + ((size_t)bt * Tc + tk) * 128) + j * 4;
        float4* dst = (float4*)(xs + r * 132) + j * 4;
        float s = 0.f, s2 = 0.f;
#pragma unroll
        for (int q = 0; q < 4; q++) {
            float4 t = src[q];
            dst[q] = t;
            s += (t.x + t.y) + (t.z + t.w);
            s2 += t.x * t.x + t.y * t.y + t.z * t.z + t.w * t.w;
        }
#pragma unroll
        for (int o = 1; o < 8; o <<= 1) {
            s  += __shfl_xor_sync(0xffffffffu, s, o);
            s2 += __shfl_xor_sync(0xffffffffu, s2, o);
        }
        if (j == 0) {
            float mu = s * (1.f / 128.f);
            float var = s2 * (1.f / 128.f) - mu * mu;
            mus[r] = mu;
            rss[r] = rsqrtf(var + 1e-5f);
        }
    }
    __syncthreads();

    int ch = tid & 15, rb = tid >> 4;    // 16 ch x 16 row-pairs
    const unsigned long long* wp = (const unsigned long long*)(gws + ch * 130);
    const unsigned long long* x0 = (const unsigned long long*)(xs + (rb * 2 + 0) * 132);
    const unsigned long long* x1 = (const unsigned long long*)(xs + (rb * 2 + 1) * 132);
    unsigned long long a0 = 0, a1 = 0;
#pragma unroll 16
    for (int f2 = 0; f2 < 64; f2++) {
        unsigned long long w = wp[f2];
        fma2(a0, x0[f2], w);
        fma2(a1, x1[f2], w);
    }
    float gs = gsum_s[ch], bw = bw_s[ch];
    float d0 = lo32(a0) + hi32(a0);
    float d1 = lo32(a1) + hi32(a1);
    int r0 = rb * 2, r1 = rb * 2 + 1;
    size_t gbase = ((size_t)bt * CAP + half * 32) * 16;
    g_z2pc[gbase + (size_t)r0 * 16 + ch] = rss[r0] * (d0 - mus[r0] * gs) + bw;
    g_z2pc[gbase + (size_t)r1 * 16 + ch] = rss[r1] * (d1 - mus[r1] * gs) + bw;
}

// ---------------- main: 1 position per thread; MLP via warp mma; straight-line ----
__global__ void __launch_bounds__(256) main_kernel(
        const float* __restrict__ ref_pos, const float* __restrict__ amask,
        const int* __restrict__ uid,
        const float* __restrict__ W_pos, const float* __restrict__ W_dist,
        const float* __restrict__ W_maskp,
        const float* __restrict__ W_m1, const float* __restrict__ W_m2,
        const float* __restrict__ W_m3,
        float* __restrict__ out) {
    __shared__ __align__(16) float sw[16 * 8];
    __shared__ unsigned stg[8 * 288];
    __shared__ __align__(16) float res[8 * 640];
    int tid = threadIdx.x;
    int lane = tid & 31, wid = tid >> 5;
    int g = lane >> 2, t = lane & 3;
    if (tid < 16) {
        sw[tid * 8 + 0] = W_pos[3 * tid];
        sw[tid * 8 + 1] = W_pos[3 * tid + 1];
        sw[tid * 8 + 2] = W_pos[3 * tid + 2];
        sw[tid * 8 + 3] = W_dist[tid];
        sw[tid * 8 + 4] = W_maskp[tid];
    }

    unsigned bf[3][4];
#pragma unroll
    for (int L = 0; L < 3; L++) {
        const float* W = (L == 0) ? W_m1 : (L == 1) ? W_m2 : W_m3;
        float2 w00 = *(const float2*)(W + g * 16 + 2 * t);
        float2 w01 = *(const float2*)(W + g * 16 + 2 * t + 8);
        float2 w10 = *(const float2*)(W + (g + 8) * 16 + 2 * t);
        float2 w11 = *(const float2*)(W + (g + 8) * 16 + 2 * t + 8);
        bf[L][0] = pkbf(w00.x, w00.y);
        bf[L][1] = pkbf(w01.x, w01.y);
        bf[L][2] = pkbf(w10.x, w10.y);
        bf[L][3] = pkbf(w11.x, w11.y);
    }
    __syncthreads();

    int gidx = blockIdx.x * 256 + tid;
    int hh = gidx & 127;
    int ww = (gidx >> 7) & 31;
    int kk = (gidx >> 12) & 127;
    int b  = gidx >> 19;
    int q = kk * 32 + ww;
    int bq = b * Nc + q;
    int key = kk * 32 + hh - 48;
    bool inr = (unsigned)key < (unsigned)Nc;
    int bk = b * Nc + (inr ? key : 0);

    float mq = amask[bq];
    float mk = inr ? amask[bk] : 0.f;
    int uq = uid[bq];
    int uk = uid[bk];
    float v = (mq != 0.f && mk != 0.f && uq == uk) ? 1.f : 0.f;

    float qx = ref_pos[bq * 3], qy = ref_pos[bq * 3 + 1], qz = ref_pos[bq * 3 + 2];
    float kx = 0.f, ky = 0.f, kz = 0.f;
    if (inr) { kx = ref_pos[bk * 3]; ky = ref_pos[bk * 3 + 1]; kz = ref_pos[bk * 3 + 2]; }
    float dx = kx - qx, dy = ky - qy, dz = kz - qz;
    float dn = 1.f / (1.f + dx * dx + dy * dy + dz * dz);

    float p[16];
#pragma unroll
    for (int d = 0; d < 16; d++) {
        float4 wv = *(const float4*)(sw + d * 8);
        float e = sw[d * 8 + 4];
        p[d] = v * (dx * wv.x + dy * wv.y + dz * wv.z + dn * wv.w + e);
    }
    {
        const float4* cq4 = (const float4*)(g_cq + (size_t)bq * 16);
#pragma unroll
        for (int i = 0; i < 4; i++) {
            float4 tt = cq4[i];
            p[4 * i] += tt.x; p[4 * i + 1] += tt.y; p[4 * i + 2] += tt.z; p[4 * i + 3] += tt.w;
        }
    }
    if (inr) {
        int tq = g_tok[bq];
        int bt = (b << 9) + tq;
        int lo = g_lo[bt];
        int zoff = bt * CAP;
        int j = g_tok[bk] - lo;
        if (j >= CAP) j = CAP - 1;     // overflow handled exactly by fixup_kernel
        const float4* zp4 = (const float4*)(g_z2pc + (size_t)(zoff + j) * 16);
        const float4* ck4 = (const float4*)(g_ck + (size_t)bk * 16);
#pragma unroll
        for (int i = 0; i < 4; i++) {
            float4 tt = zp4[i], u = ck4[i];
            p[4 * i]     += tt.x + u.x;
            p[4 * i + 1] += tt.y + u.y;
            p[4 * i + 2] += tt.z + u.z;
            p[4 * i + 3] += tt.w + u.w;
        }
    }

    unsigned* h2 = stg + wid * 288;
#pragma unroll
    for (int j2 = 0; j2 < 8; j2++)
        h2[lane * 9 + j2] = pkbf(fmaxf(p[2 * j2], 0.f), fmaxf(p[2 * j2 + 1], 0.f));
    __syncwarp();

    unsigned a0[2], a1[2], a2[2], a3[2];
#pragma unroll
    for (int tt = 0; tt < 2; tt++) {
        int rt = tt * 16;
        a0[tt] = h2[(rt + g) * 9 + t];
        a1[tt] = h2[(rt + g + 8) * 9 + t];
        a2[tt] = h2[(rt + g) * 9 + t + 4];
        a3[tt] = h2[(rt + g + 8) * 9 + t + 4];
    }
    __syncwarp();

    float* wsm = res + wid * 640;
#pragma unroll
    for (int tt = 0; tt < 2; tt++) {
        unsigned u0 = a0[tt], u1 = a1[tt], u2 = a2[tt], u3 = a3[tt];
        float dlo[4], dhi[4];
#pragma unroll
        for (int L = 0; L < 3; L++) {
            mma16816(dlo, u0, u1, u2, u3, bf[L][0], bf[L][1]);
            mma16816(dhi, u0, u1, u2, u3, bf[L][2], bf[L][3]);
            if (L < 2) {
                u0 = pkbf(fmaxf(dlo[0], 0.f), fmaxf(dlo[1], 0.f));
                u1 = pkbf(fmaxf(dlo[2], 0.f), fmaxf(dlo[3], 0.f));
                u2 = pkbf(fmaxf(dhi[0], 0.f), fmaxf(dhi[1], 0.f));
                u3 = pkbf(fmaxf(dhi[2], 0.f), fmaxf(dhi[3], 0.f));
            }
        }
        int r0 = tt * 16 + g, r1 = r0 + 8;
        *(float2*)(wsm + r0 * 20 + 2 * t)     = make_float2(dlo[0], dlo[1]);
        *(float2*)(wsm + r1 * 20 + 2 * t)     = make_float2(dlo[2], dlo[3]);
        *(float2*)(wsm + r0 * 20 + 8 + 2 * t) = make_float2(dhi[0], dhi[1]);
        *(float2*)(wsm + r1 * 20 + 8 + 2 * t) = make_float2(dhi[2], dhi[3]);
    }
    __syncwarp();

    float4* o4 = (float4*)(out + (size_t)gidx * 16);
    const float4* mrow = (const float4*)(wsm + lane * 20);
#pragma unroll
    for (int i = 0; i < 4; i++) {
        float4 mi = mrow[i];
        __stcs(o4 + i, make_float4(p[4 * i] + mi.x, p[4 * i + 1] + mi.y,
                                   p[4 * i + 2] + mi.z, p[4 * i + 3] + mi.w));
    }
}

// ---------------- fixup: exact recompute of window-overflow positions (rare) ----------
__global__ void fixup_kernel(
        const float* __restrict__ ref_pos, const float* __restrict__ amask,
        const int* __restrict__ uid, const float* __restrict__ z,
        const float* __restrict__ W_pos, const float* __restrict__ W_dist,
        const float* __restrict__ W_maskp,
        const float* __restrict__ W_m1, const float* __restrict__ W_m2,
        const float* __restrict__ W_m3,
        float* __restrict__ out) {
    if (!g_anyovf) return;
    int bt = blockIdx.x;
    int amx = g_amax[bt];
    if (amx < 0) return;
    int amn = g_amin[bt];
    int b = bt >> 9;
    int alo = 32 * (amn >> 5) - 48; if (alo < 0) alo = 0;
    int ahi = 32 * (amx >> 5) + 79; if (ahi > Nc - 1) ahi = Nc - 1;
    int lo = g_tok[b * Nc + alo];
    int hi = g_tok[b * Nc + ahi];
    if (hi - lo < CAP) return;

    int hh = threadIdx.x;
    for (int q = amn; q <= amx; q++) {
        int kk = q >> 5;
        int key = kk * 32 + hh - 48;
        if ((unsigned)key >= (unsigned)Nc) continue;
        int bq = b * Nc + q;
        int bk = b * Nc + key;
        int tk2 = g_tok[bk];
        if (tk2 - lo < CAP) continue;

        float mq = amask[bq], mk = amask[bk];
        float vv = (mq != 0.f && mk != 0.f && uid[bq] == uid[bk]) ? 1.f : 0.f;
        float dx = ref_pos[bk * 3] - ref_pos[bq * 3];
        float dy = ref_pos[bk * 3 + 1] - ref_pos[bq * 3 + 1];
        float dz = ref_pos[bk * 3 + 2] - ref_pos[bq * 3 + 2];
        float dn = 1.f / (1.f + dx * dx + dy * dy + dz * dz);

        const float* zrow = z + ((size_t)bt * Tc + tk2) * 128;
        float s = 0.f, s2 = 0.f;
        for (int f = 0; f < 128; f++) { float x = zrow[f]; s += x; s2 += x * x; }
        float mu = s * (1.f / 128.f);
        float rs = rsqrtf(s2 * (1.f / 128.f) - mu * mu + 1e-5f);

        float p[16];
        for (int d = 0; d < 16; d++) {
            float dot = 0.f;
            for (int f = 0; f < 128; f++) dot += zrow[f] * g_gw[d * 128 + f];
            float zc = rs * (dot - mu * g_gsum[d]) + g_bw[d];
            p[d] = vv * (dx * W_pos[3 * d] + dy * W_pos[3 * d + 1] + dz * W_pos[3 * d + 2]
                         + dn * W_dist[d] + W_maskp[d])
                   + g_cq[(size_t)bq * 16 + d] + g_ck[(size_t)bk * 16 + d] + zc;
        }
        float r0[16], r1[16], r2[16];
        for (int i = 0; i < 16; i++) {
            float a = 0.f;
            for (int j = 0; j < 16; j++) a += fmaxf(p[j], 0.f) * W_m1[i * 16 + j];
            r0[i] = a;
        }
        for (int i = 0; i < 16; i++) {
            float a = 0.f;
            for (int j = 0; j < 16; j++) a += fmaxf(r0[j], 0.f) * W_m2[i * 16 + j];
            r1[i] = a;
        }
        for (int i = 0; i < 16; i++) {
            float a = 0.f;
            for (int j = 0; j < 16; j++) a += fmaxf(r1[j], 0.f) * W_m3[i * 16 + j];
            r2[i] = a;
        }
        size_t gidx = ((size_t)b << 19) | ((size_t)kk << 12) | ((size_t)(q & 31) << 7) | hh;
        float* o = out + gidx * 16;
        for (int i = 0; i < 16; i++) o[i] = p[i] + r2[i];
    }
}

// ---------------- launch ----------------
extern "C" void kernel_launch(void* const* d_in, const int* in_sizes, int n_in,
                              void* d_out, int out_size) {
    const float* ref_pos             = (const float*)d_in[0];
    const float* ref_charge          = (const float*)d_in[1];
    const float* atom_pad_mask       = (const float*)d_in[2];
    const float* ref_element         = (const float*)d_in[3];
    const float* ref_atom_name_chars = (const float*)d_in[4];
    const int*   ref_space_uid       = (const int*)  d_in[5];
    const float* atom_to_token       = (const float*)d_in[6];
    const float* s_trunk             = (const float*)d_in[7];
    const float* z                   = (const float*)d_in[8];
    const float* W_feat              = (const float*)d_in[9];
    const float* W_pos               = (const float*)d_in[10];
    const float* W_dist              = (const float*)d_in[11];
    const float* W_maskp             = (const float*)d_in[12];
    const float* ln_s_g              = (const float*)d_in[13];
    const float* ln_s_b              = (const float*)d_in[14];
    const float* W_s2c               = (const float*)d_in[15];
    const float* ln_z_g              = (const float*)d_in[16];
    const float* ln_z_b              = (const float*)d_in[17];
    const float* W_z2p               = (const float*)d_in[18];
    const float* W_cq                = (const float*)d_in[19];
    const float* W_ck                = (const float*)d_in[20];
    const float* W_m1                = (const float*)d_in[21];
    const float* W_m2                = (const float*)d_in[22];
    const float* W_m3                = (const float*)d_in[23];
    float* out = (float*)d_out;

    prep_kernel<<<64, 256>>>(W_feat, W_s2c, W_z2p, ln_z_g, ln_z_b);
    tok_s2c_kernel<<<1536, 256>>>(atom_to_token, s_trunk, ln_s_g, ln_s_b);
    c_kernel<<<(Bc * Nc) / 8, 256>>>(ref_pos, ref_charge, atom_pad_mask,
                                     ref_element, ref_atom_name_chars, W_cq, W_ck);
    z2pc_kernel<<<2 * Bc * Tc, 256>>>(z);
    main_kernel<<<(Bc * 128 * 32 * 128) / 256, 256>>>(ref_pos, atom_pad_mask, ref_space_uid,
                                                      W_pos, W_dist, W_maskp,
                                                      W_m1, W_m2, W_m3, out);
    fixup_kernel<<<Bc * Tc, 128>>>(ref_pos, atom_pad_mask, ref_space_uid, z,
                                   W_pos, W_dist, W_maskp, W_m1, W_m2, W_m3, out);
}

// round 13
// speedup vs baseline: 1.0944x; 1.0115x over previous
#include <cuda_runtime.h>
#include <cstdint>

#define Bc 2
#define Nc 4096
#define Tc 512
#define CAP 64

// ---------------- scratch (static device globals; no allocation) ----------------
__device__ float  g_s2c[Bc * Tc * 128];                 // s_to_c
__device__ int    g_tok[Bc * Nc];                       // token index per atom
__device__ float  g_cq[Bc * Nc * 16];                   // relu(c) @ W_cq.T
__device__ float  g_ck[Bc * Nc * 16];                   // relu(c) @ W_ck.T
__device__ float  g_z2pc[(size_t)Bc * Tc * CAP * 16];   // compact z2p window (4 MB)
__device__ int    g_lo[Bc * Tc];                        // key-token window start per (b,tq)
__device__ int    g_amin[Bc * Tc];
__device__ int    g_amax[Bc * Tc];
__device__ int    g_anyovf;                             // any (b,tq) window exceeded CAP?
__device__ float2 g_WfP2[196 * 128];                    // (w[2f2][ch], w[2f2+1][ch]) non-dup
__device__ float  g_Ws2cT[384 * 128];
__device__ float  g_gw[16 * 128];                       // W_z2p * ln_z_g (folded, f32: fixup)
__device__ float  g_gwh[16 * 128];                      // tf32-high part of g_gw
__device__ float  g_gwl[16 * 128];                      // tf32 residual of g_gw
__device__ float  g_gsum[16];
__device__ float  g_bw[16];

// ---------------- f32x2 / bf16 / tf32 helpers ----------------
__device__ __forceinline__ void fma2(unsigned long long& acc, unsigned long long a, unsigned long long b) {
    asm("fma.rn.f32x2 %0, %1, %2, %0;" : "+l"(acc) : "l"(a), "l"(b));
}
__device__ __forceinline__ unsigned long long dup2(float w) {
    unsigned long long r;
    asm("mov.b64 %0, {%1,%1};" : "=l"(r) : "f"(w));
    return r;
}
__device__ __forceinline__ float lo32(unsigned long long v) { return __uint_as_float((unsigned)(v & 0xffffffffu)); }
__device__ __forceinline__ float hi32(unsigned long long v) { return __uint_as_float((unsigned)(v >> 32)); }
__device__ __forceinline__ unsigned pkbf(float lo, float hi) {
    unsigned r;
    asm("cvt.rn.bf16x2.f32 %0, %1, %2;" : "=r"(r) : "f"(hi), "f"(lo));
    return r;
}
__device__ __forceinline__ unsigned t32(float x) {
    unsigned r;
    asm("cvt.rna.tf32.f32 %0, %1;" : "=r"(r) : "f"(x));
    return r;
}
__device__ __forceinline__ void mma16816(float* d, unsigned a0, unsigned a1, unsigned a2, unsigned a3,
                                         unsigned b0, unsigned b1) {
    asm("mma.sync.aligned.m16n8k16.row.col.f32.bf16.bf16.f32 "
        "{%0,%1,%2,%3}, {%4,%5,%6,%7}, {%8,%9}, {%10,%11,%12,%13};"
        : "=f"(d[0]), "=f"(d[1]), "=f"(d[2]), "=f"(d[3])
        : "r"(a0), "r"(a1), "r"(a2), "r"(a3), "r"(b0), "r"(b1),
          "f"(0.f), "f"(0.f), "f"(0.f), "f"(0.f));
}
__device__ __forceinline__ void mma_tf32(float* d, unsigned a0, unsigned a1, unsigned a2, unsigned a3,
                                         unsigned b0, unsigned b1) {
    asm("mma.sync.aligned.m16n8k8.row.col.f32.tf32.tf32.f32 "
        "{%0,%1,%2,%3}, {%4,%5,%6,%7}, {%8,%9}, {%0,%1,%2,%3};"
        : "+f"(d[0]), "+f"(d[1]), "+f"(d[2]), "+f"(d[3])
        : "r"(a0), "r"(a1), "r"(a2), "r"(a3), "r"(b0), "r"(b1));
}

// ---------------- prep: weight tables + layernorm fold + range/flag init ----------------
__global__ void prep_kernel(const float* __restrict__ W_feat, const float* __restrict__ W_s2c,
                            const float* __restrict__ W_z2p, const float* __restrict__ ln_z_g,
                            const float* __restrict__ ln_z_b) {
    int t = blockIdx.x * blockDim.x + threadIdx.x;
    int nt = gridDim.x * blockDim.x;
    for (int i = t; i < 196 * 128; i += nt) {
        int f2 = i >> 7, ch = i & 127;
        int fi0 = 2 * f2, fi1 = fi0 + 1;
        float w0 = (fi0 < 389) ? W_feat[ch * 389 + fi0] : 0.f;
        float w1 = (fi1 < 389) ? W_feat[ch * 389 + fi1] : 0.f;
        g_WfP2[i] = make_float2(w0, w1);
    }
    for (int i = t; i < 384 * 128; i += nt) {
        int ch = i / 384, f = i % 384;
        g_Ws2cT[f * 128 + ch] = W_s2c[i];
    }
    for (int i = t; i < 16 * 128; i += nt) {
        float w = W_z2p[i] * ln_z_g[i & 127];
        g_gw[i] = w;
        float wh = __uint_as_float(t32(w));
        g_gwh[i] = wh;
        g_gwl[i] = __uint_as_float(t32(w - wh));
    }
    for (int i = t; i < Bc * Tc; i += nt) { g_amin[i] = Nc; g_amax[i] = -1; }
    if (t == 0) g_anyovf = 0;
    if (t < 16) {
        float gs = 0.f, bw = 0.f;
        for (int f = 0; f < 128; f++) {
            gs += W_z2p[t * 128 + f] * ln_z_g[f];
            bw += W_z2p[t * 128 + f] * ln_z_b[f];
        }
        g_gsum[t] = gs;
        g_bw[t] = bw;
    }
}

// ---- fused: blocks [0,1024): token argmax + atom-range; blocks [1024,1536): s2c 2 rows ----
__global__ void __launch_bounds__(256) tok_s2c_kernel(
        const float* __restrict__ a2t, const float* __restrict__ s_trunk,
        const float* __restrict__ g, const float* __restrict__ bta) {
    __shared__ __align__(16) float xs2[2][384];
    __shared__ float red2[2][8];
    int tid = threadIdx.x;

    if (blockIdx.x < 1024) {
        int warp = blockIdx.x * 8 + (tid >> 5);
        int lane = tid & 31;
        const float4* row = (const float4*)(a2t + (size_t)warp * Tc);
        int idx = 0;
#pragma unroll
        for (int i = 0; i < 4; i++) {
            float4 v = row[lane + 32 * i];
            int base = 4 * (lane + 32 * i);
            if (v.x > 0.5f) idx = base;
            if (v.y > 0.5f) idx = base + 1;
            if (v.z > 0.5f) idx = base + 2;
            if (v.w > 0.5f) idx = base + 3;
        }
#pragma unroll
        for (int o = 16; o; o >>= 1) idx = max(idx, __shfl_xor_sync(0xffffffffu, idx, o));
        if (lane == 0) {
            g_tok[warp] = idx;
            int b = warp >> 12;
            int al = warp & (Nc - 1);
            atomicMin(&g_amin[b * Tc + idx], al);
            atomicMax(&g_amax[b * Tc + idx], al);
        }
        return;
    }

    int half = tid >> 7;
    int t2 = tid & 127;
    int row = (blockIdx.x - 1024) * 2 + half;
    const float* x = s_trunk + (size_t)row * 384;
    float v0 = x[t2], v1 = x[t2 + 128], v2 = x[t2 + 256];
    float s = v0 + v1 + v2, s2 = v0 * v0 + v1 * v1 + v2 * v2;
#pragma unroll
    for (int o = 16; o; o >>= 1) {
        s += __shfl_xor_sync(0xffffffffu, s, o);
        s2 += __shfl_xor_sync(0xffffffffu, s2, o);
    }
    if ((t2 & 31) == 0) { red2[half][t2 >> 5] = s; red2[half][4 + (t2 >> 5)] = s2; }
    __syncthreads();
    s = red2[half][0] + red2[half][1] + red2[half][2] + red2[half][3];
    s2 = red2[half][4] + red2[half][5] + red2[half][6] + red2[half][7];
    float mu = s * (1.f / 384.f);
    float var = s2 * (1.f / 384.f) - mu * mu;
    float rs = rsqrtf(var + 1e-5f);
    xs2[half][t2]       = (v0 - mu) * rs * g[t2]       + bta[t2];
    xs2[half][t2 + 128] = (v1 - mu) * rs * g[t2 + 128] + bta[t2 + 128];
    xs2[half][t2 + 256] = (v2 - mu) * rs * g[t2 + 256] + bta[t2 + 256];
    __syncthreads();
    float acc = 0.f;
#pragma unroll 4
    for (int f = 0; f < 384; f++) acc += xs2[half][f] * g_Ws2cT[f * 128 + t2];
    g_s2c[(size_t)row * 128 + t2] = acc;
}

// ---- c embedding + cq/ck heads: 8 atoms/block (grid 1024), LDG.64 weights + reg-dup ----
// (R8/R10-measured winner: 52.5us, occ ~80%)
__global__ void __launch_bounds__(256) c_kernel(
        const float* __restrict__ ref_pos, const float* __restrict__ ref_charge,
        const float* __restrict__ amask, const float* __restrict__ elem,
        const float* __restrict__ chars,
        const float* __restrict__ W_cq, const float* __restrict__ W_ck) {
    __shared__ __align__(16) float sm[5200];
    __shared__ int ts[8];
    int tid = threadIdx.x;
    int abase = blockIdx.x * 8;

#pragma unroll
    for (int pass = 0; pass < 2; pass++) {
        int fi = tid + pass * 256;
        if (fi < 392) {
            float* row = sm + fi * 12;
#pragma unroll 4
            for (int a = 0; a < 8; a++) {
                int atom = abase + a;
                float v;
                if (fi < 3)        v = ref_pos[atom * 3 + fi];
                else if (fi == 3)  v = ref_charge[atom];
                else if (fi == 4)  v = amask[atom];
                else if (fi < 133) v = elem[(size_t)atom * 128 + (fi - 5)];
                else if (fi < 389) v = chars[(size_t)atom * 256 + (fi - 133)];
                else               v = 0.f;
                row[a] = v;
            }
        }
    }
    if (tid < 8) ts[tid] = g_tok[abase + tid];
    __syncthreads();

    int ch = tid & 127;
    int half = tid >> 7;                   // 0: atoms 0..3, 1: atoms 4..7
    const float2* wp = (const float2*)g_WfP2 + ch;
    const char* fb = (const char*)sm + half * 16;
    unsigned long long acc0 = 0, acc1 = 0;
#pragma unroll 8
    for (int f2 = 0; f2 < 196; f2++) {
        float2 ww = wp[(size_t)f2 * 128];
        unsigned long long w0d = dup2(ww.x);
        unsigned long long w1d = dup2(ww.y);
        const char* r0 = fb + (size_t)f2 * 96;
        ulonglong2 fa = *(const ulonglong2*)(r0);
        ulonglong2 fc = *(const ulonglong2*)(r0 + 48);
        fma2(acc0, fa.x, w0d); fma2(acc1, fa.y, w0d);
        fma2(acc0, fc.x, w1d); fma2(acc1, fc.y, w1d);
    }

    int bb = abase >> 12;
    const float* srow = g_s2c + (size_t)bb * Tc * 128 + ch;
    int a0 = half * 4;
    float cv0 = fmaxf(lo32(acc0) + srow[(size_t)ts[a0]     * 128], 0.f);
    float cv1 = fmaxf(hi32(acc0) + srow[(size_t)ts[a0 + 1] * 128], 0.f);
    float cv2 = fmaxf(lo32(acc1) + srow[(size_t)ts[a0 + 2] * 128], 0.f);
    float cv3 = fmaxf(hi32(acc1) + srow[(size_t)ts[a0 + 3] * 128], 0.f);
    __syncthreads();

    float* cs  = sm;                        // [8][128]
    float* wcs = sm + 1024;                 // [2][16][130]
    cs[(a0 + 0) * 128 + ch] = cv0;
    cs[(a0 + 1) * 128 + ch] = cv1;
    cs[(a0 + 2) * 128 + ch] = cv2;
    cs[(a0 + 3) * 128 + ch] = cv3;
    for (int idx = tid; idx < 2 * 16 * 128; idx += 256) {
        int which = idx >> 11, i = (idx >> 7) & 15, chh = idx & 127;
        wcs[(which * 16 + i) * 130 + chh] = which ? W_ck[i * 128 + chh] : W_cq[i * 128 + chh];
    }
    __syncthreads();

    int i = tid & 15, which = (tid >> 4) & 1, a = tid >> 5;
    const unsigned long long* wr = (const unsigned long long*)(wcs + (which * 16 + i) * 130);
    const unsigned long long* cr = (const unsigned long long*)(cs + a * 128);
    unsigned long long s = 0;
#pragma unroll 16
    for (int t2 = 0; t2 < 64; t2++) fma2(s, cr[t2], wr[t2]);
    float* dst = which ? g_ck : g_cq;
    dst[(size_t)(abase + a) * 16 + i] = lo32(s) + hi32(s);
}

// ---- compact z_to_p: 2 blocks per (b,tq), 32 rows each; tf32x3 tensor-core dot ----
__global__ void __launch_bounds__(256) z2pc_kernel(const float* __restrict__ z) {
    __shared__ __align__(16) float xs[32 * 132];
    __shared__ __align__(16) float gwh[16 * 130];
    __shared__ __align__(16) float gwl[16 * 130];
    __shared__ __align__(16) float pd[4 * 32 * 4];
    __shared__ float mus[32], rss[32], gsum_s[16], bw_s[16];
    __shared__ int lo_s;
    int tid = threadIdx.x;
    int bt = blockIdx.x >> 1;            // b*Tc + tq
    int half = blockIdx.x & 1;           // rows [half*32, half*32+32)

    if (tid == 0) {
        int lo = 0;
        int amx = g_amax[bt];
        if (amx >= 0) {
            int amn = g_amin[bt];
            int alo = 32 * (amn >> 5) - 48; if (alo < 0) alo = 0;
            int ahi = 32 * (amx >> 5) + 79; if (ahi > Nc - 1) ahi = Nc - 1;
            int bO = (bt >> 9) * Nc;
            lo = g_tok[bO + alo];
            if (half == 0) {
                int hi = g_tok[bO + ahi];
                g_lo[bt] = lo;
                if (hi - lo >= CAP) g_anyovf = 1;
            }
        } else if (half == 0) {
            g_lo[bt] = 0;
        }
        lo_s = lo;
    }
    for (int i = tid; i < 2048; i += 256) {
        int r = (i >> 7) * 130 + (i & 127);
        gwh[r] = g_gwh[i];
        gwl[r] = g_gwl[i];
    }
    if (tid < 16) { gsum_s[tid] = g_gsum[tid]; bw_s[tid] = g_bw[tid]; }
    __syncthreads();
    int lo = lo_s;

    {   // phase 1: load 32 rows (contiguous in z), per-row mean/var; 8 threads/row
        int r = tid >> 3, j = tid & 7;
        int tk = lo + half * 32 + r;
        if (tk > Tc - 1) tk = Tc - 1;
        const float4* src = (const float4*)(z + ((size_t)bt * Tc + tk) * 128) + j * 4;
        float4* dst = (float4*)(xs + r * 132) + j * 4;
        float s = 0.f, s2 = 0.f;
#pragma unroll
        for (int q = 0; q < 4; q++) {
            float4 t = src[q];
            dst[q] = t;
            s += (t.x + t.y) + (t.z + t.w);
            s2 += t.x * t.x + t.y * t.y + t.z * t.z + t.w * t.w;
        }
#pragma unroll
        for (int o = 1; o < 8; o <<= 1) {
            s  += __shfl_xor_sync(0xffffffffu, s, o);
            s2 += __shfl_xor_sync(0xffffffffu, s2, o);
        }
        if (j == 0) {
            float mu = s * (1.f / 128.f);
            float var = s2 * (1.f / 128.f) - mu * mu;
            mus[r] = mu;
            rss[r] = rsqrtf(var + 1e-5f);
        }
    }
    __syncthreads();

    // phase 2: D[32x16] = xs[32x128] * gw^T via m16n8k8 tf32 (tf32x3 for f32 accuracy)
    int lane = tid & 31, wid = tid >> 5;
    int g2 = lane >> 2, t = lane & 3;
    int mn = wid & 3, kh = wid >> 2;      // mn: (m-tile, n-tile); kh: k-half
    int rb = (mn >> 1) * 16;              // row base 0/16
    int cb = (mn & 1) * 8;                // ch base 0/8
    const float* xr0 = xs + (rb + g2) * 132;
    const float* xr1 = xs + (rb + g2 + 8) * 132;
    const unsigned* bhp = (const unsigned*)(gwh + (cb + g2) * 130);
    const unsigned* blp = (const unsigned*)(gwl + (cb + g2) * 130);
    float D[4] = { 0.f, 0.f, 0.f, 0.f };
#pragma unroll
    for (int kc = 0; kc < 8; kc++) {
        int k0 = (kh * 8 + kc) * 8;
        float f0 = xr0[k0 + t],     f1 = xr1[k0 + t];
        float f2 = xr0[k0 + t + 4], f3 = xr1[k0 + t + 4];
        unsigned ah0 = t32(f0), ah1 = t32(f1), ah2 = t32(f2), ah3 = t32(f3);
        unsigned al0 = t32(f0 - __uint_as_float(ah0));
        unsigned al1 = t32(f1 - __uint_as_float(ah1));
        unsigned al2 = t32(f2 - __uint_as_float(ah2));
        unsigned al3 = t32(f3 - __uint_as_float(ah3));
        unsigned bh0 = bhp[k0 + t], bh1 = bhp[k0 + t + 4];
        unsigned bl0 = blp[k0 + t], bl1 = blp[k0 + t + 4];
        mma_tf32(D, ah0, ah1, ah2, ah3, bh0, bh1);
        mma_tf32(D, al0, al1, al2, al3, bh0, bh1);
        mma_tf32(D, ah0, ah1, ah2, ah3, bl0, bl1);
    }
    if (kh == 1) {
        float* p = pd + (mn * 32 + lane) * 4;
        p[0] = D[0]; p[1] = D[1]; p[2] = D[2]; p[3] = D[3];
    }
    __syncthreads();
    if (kh == 0) {
        const float* p = pd + (mn * 32 + lane) * 4;
        D[0] += p[0]; D[1] += p[1]; D[2] += p[2]; D[3] += p[3];
        int lr0 = rb + g2, lr1 = lr0 + 8;
        int c0 = cb + 2 * t, c1 = c0 + 1;
        float* ob = g_z2pc + ((size_t)bt * CAP + half * 32) * 16;
        ob[lr0 * 16 + c0] = rss[lr0] * (D[0] - mus[lr0] * gsum_s[c0]) + bw_s[c0];
        ob[lr0 * 16 + c1] = rss[lr0] * (D[1] - mus[lr0] * gsum_s[c1]) + bw_s[c1];
        ob[lr1 * 16 + c0] = rss[lr1] * (D[2] - mus[lr1] * gsum_s[c0]) + bw_s[c0];
        ob[lr1 * 16 + c1] = rss[lr1] * (D[3] - mus[lr1] * gsum_s[c1]) + bw_s[c1];
    }
}

// ---------------- main: 1 position per thread; MLP via warp mma; straight-line ----
__global__ void __launch_bounds__(256) main_kernel(
        const float* __restrict__ ref_pos, const float* __restrict__ amask,
        const int* __restrict__ uid,
        const float* __restrict__ W_pos, const float* __restrict__ W_dist,
        const float* __restrict__ W_maskp,
        const float* __restrict__ W_m1, const float* __restrict__ W_m2,
        const float* __restrict__ W_m3,
        float* __restrict__ out) {
    __shared__ __align__(16) float sw[16 * 8];
    __shared__ unsigned stg[8 * 288];
    __shared__ __align__(16) float res[8 * 640];
    int tid = threadIdx.x;
    int lane = tid & 31, wid = tid >> 5;
    int g = lane >> 2, t = lane & 3;
    if (tid < 16) {
        sw[tid * 8 + 0] = W_pos[3 * tid];
        sw[tid * 8 + 1] = W_pos[3 * tid + 1];
        sw[tid * 8 + 2] = W_pos[3 * tid + 2];
        sw[tid * 8 + 3] = W_dist[tid];
        sw[tid * 8 + 4] = W_maskp[tid];
    }

    unsigned bf[3][4];
#pragma unroll
    for (int L = 0; L < 3; L++) {
        const float* W = (L == 0) ? W_m1 : (L == 1) ? W_m2 : W_m3;
        float2 w00 = *(const float2*)(W + g * 16 + 2 * t);
        float2 w01 = *(const float2*)(W + g * 16 + 2 * t + 8);
        float2 w10 = *(const float2*)(W + (g + 8) * 16 + 2 * t);
        float2 w11 = *(const float2*)(W + (g + 8) * 16 + 2 * t + 8);
        bf[L][0] = pkbf(w00.x, w00.y);
        bf[L][1] = pkbf(w01.x, w01.y);
        bf[L][2] = pkbf(w10.x, w10.y);
        bf[L][3] = pkbf(w11.x, w11.y);
    }
    __syncthreads();

    int gidx = blockIdx.x * 256 + tid;
    int hh = gidx & 127;
    int ww = (gidx >> 7) & 31;
    int kk = (gidx >> 12) & 127;
    int b  = gidx >> 19;
    int q = kk * 32 + ww;
    int bq = b * Nc + q;
    int key = kk * 32 + hh - 48;
    bool inr = (unsigned)key < (unsigned)Nc;
    int bk = b * Nc + (inr ? key : 0);

    float mq = amask[bq];
    float mk = inr ? amask[bk] : 0.f;
    int uq = uid[bq];
    int uk = uid[bk];
    float v = (mq != 0.f && mk != 0.f && uq == uk) ? 1.f : 0.f;

    float qx = ref_pos[bq * 3], qy = ref_pos[bq * 3 + 1], qz = ref_pos[bq * 3 + 2];
    float kx = 0.f, ky = 0.f, kz = 0.f;
    if (inr) { kx = ref_pos[bk * 3]; ky = ref_pos[bk * 3 + 1]; kz = ref_pos[bk * 3 + 2]; }
    float dx = kx - qx, dy = ky - qy, dz = kz - qz;
    float dn = 1.f / (1.f + dx * dx + dy * dy + dz * dz);

    float p[16];
#pragma unroll
    for (int d = 0; d < 16; d++) {
        float4 wv = *(const float4*)(sw + d * 8);
        float e = sw[d * 8 + 4];
        p[d] = v * (dx * wv.x + dy * wv.y + dz * wv.z + dn * wv.w + e);
    }
    {
        const float4* cq4 = (const float4*)(g_cq + (size_t)bq * 16);
#pragma unroll
        for (int i = 0; i < 4; i++) {
            float4 tt = cq4[i];
            p[4 * i] += tt.x; p[4 * i + 1] += tt.y; p[4 * i + 2] += tt.z; p[4 * i + 3] += tt.w;
        }
    }
    if (inr) {
        int tq = g_tok[bq];
        int bt = (b << 9) + tq;
        int lo = g_lo[bt];
        int zoff = bt * CAP;
        int j = g_tok[bk] - lo;
        if (j >= CAP) j = CAP - 1;     // overflow handled exactly by fixup_kernel
        const float4* zp4 = (const float4*)(g_z2pc + (size_t)(zoff + j) * 16);
        const float4* ck4 = (const float4*)(g_ck + (size_t)bk * 16);
#pragma unroll
        for (int i = 0; i < 4; i++) {
            float4 tt = zp4[i], u = ck4[i];
            p[4 * i]     += tt.x + u.x;
            p[4 * i + 1] += tt.y + u.y;
            p[4 * i + 2] += tt.z + u.z;
            p[4 * i + 3] += tt.w + u.w;
        }
    }

    unsigned* h2 = stg + wid * 288;
#pragma unroll
    for (int j2 = 0; j2 < 8; j2++)
        h2[lane * 9 + j2] = pkbf(fmaxf(p[2 * j2], 0.f), fmaxf(p[2 * j2 + 1], 0.f));
    __syncwarp();

    unsigned a0[2], a1[2], a2[2], a3[2];
#pragma unroll
    for (int tt = 0; tt < 2; tt++) {
        int rt = tt * 16;
        a0[tt] = h2[(rt + g) * 9 + t];
        a1[tt] = h2[(rt + g + 8) * 9 + t];
        a2[tt] = h2[(rt + g) * 9 + t + 4];
        a3[tt] = h2[(rt + g + 8) * 9 + t + 4];
    }
    __syncwarp();

    float* wsm = res + wid * 640;
#pragma unroll
    for (int tt = 0; tt < 2; tt++) {
        unsigned u0 = a0[tt], u1 = a1[tt], u2 = a2[tt], u3 = a3[tt];
        float dlo[4], dhi[4];
#pragma unroll
        for (int L = 0; L < 3; L++) {
            mma16816(dlo, u0, u1, u2, u3, bf[L][0], bf[L][1]);
            mma16816(dhi, u0, u1, u2, u3, bf[L][2], bf[L][3]);
            if (L < 2) {
                u0 = pkbf(fmaxf(dlo[0], 0.f), fmaxf(dlo[1], 0.f));
                u1 = pkbf(fmaxf(dlo[2], 0.f), fmaxf(dlo[3], 0.f));
                u2 = pkbf(fmaxf(dhi[0], 0.f), fmaxf(dhi[1], 0.f));
                u3 = pkbf(fmaxf(dhi[2], 0.f), fmaxf(dhi[3], 0.f));
            }
        }
        int r0 = tt * 16 + g, r1 = r0 + 8;
        *(float2*)(wsm + r0 * 20 + 2 * t)     = make_float2(dlo[0], dlo[1]);
        *(float2*)(wsm + r1 * 20 + 2 * t)     = make_float2(dlo[2], dlo[3]);
        *(float2*)(wsm + r0 * 20 + 8 + 2 * t) = make_float2(dhi[0], dhi[1]);
        *(float2*)(wsm + r1 * 20 + 8 + 2 * t) = make_float2(dhi[2], dhi[3]);
    }
    __syncwarp();

    float4* o4 = (float4*)(out + (size_t)gidx * 16);
    const float4* mrow = (const float4*)(wsm + lane * 20);
#pragma unroll
    for (int i = 0; i < 4; i++) {
        float4 mi = mrow[i];
        __stcs(o4 + i, make_float4(p[4 * i] + mi.x, p[4 * i + 1] + mi.y,
                                   p[4 * i + 2] + mi.z, p[4 * i + 3] + mi.w));
    }
}

// ---------------- fixup: exact recompute of window-overflow positions (rare) ----------
__global__ void fixup_kernel(
        const float* __restrict__ ref_pos, const float* __restrict__ amask,
        const int* __restrict__ uid, const float* __restrict__ z,
        const float* __restrict__ W_pos, const float* __restrict__ W_dist,
        const float* __restrict__ W_maskp,
        const float* __restrict__ W_m1, const float* __restrict__ W_m2,
        const float* __restrict__ W_m3,
        float* __restrict__ out) {
    if (!g_anyovf) return;
    int bt = blockIdx.x;
    int amx = g_amax[bt];
    if (amx < 0) return;
    int amn = g_amin[bt];
    int b = bt >> 9;
    int alo = 32 * (amn >> 5) - 48; if (alo < 0) alo = 0;
    int ahi = 32 * (amx >> 5) + 79; if (ahi > Nc - 1) ahi = Nc - 1;
    int lo = g_tok[b * Nc + alo];
    int hi = g_tok[b * Nc + ahi];
    if (hi - lo < CAP) return;

    int hh = threadIdx.x;
    for (int q = amn; q <= amx; q++) {
        int kk = q >> 5;
        int key = kk * 32 + hh - 48;
        if ((unsigned)key >= (unsigned)Nc) continue;
        int bq = b * Nc + q;
        int bk = b * Nc + key;
        int tk2 = g_tok[bk];
        if (tk2 - lo < CAP) continue;

        float mq = amask[bq], mk = amask[bk];
        float vv = (mq != 0.f && mk != 0.f && uid[bq] == uid[bk]) ? 1.f : 0.f;
        float dx = ref_pos[bk * 3] - ref_pos[bq * 3];
        float dy = ref_pos[bk * 3 + 1] - ref_pos[bq * 3 + 1];
        float dz = ref_pos[bk * 3 + 2] - ref_pos[bq * 3 + 2];
        float dn = 1.f / (1.f + dx * dx + dy * dy + dz * dz);

        const float* zrow = z + ((size_t)bt * Tc + tk2) * 128;
        float s = 0.f, s2 = 0.f;
        for (int f = 0; f < 128; f++) { float x = zrow[f]; s += x; s2 += x * x; }
        float mu = s * (1.f / 128.f);
        float rs = rsqrtf(s2 * (1.f / 128.f) - mu * mu + 1e-5f);

        float p[16];
        for (int d = 0; d < 16; d++) {
            float dot = 0.f;
            for (int f = 0; f < 128; f++) dot += zrow[f] * g_gw[d * 128 + f];
            float zc = rs * (dot - mu * g_gsum[d]) + g_bw[d];
            p[d] = vv * (dx * W_pos[3 * d] + dy * W_pos[3 * d + 1] + dz * W_pos[3 * d + 2]
                         + dn * W_dist[d] + W_maskp[d])
                   + g_cq[(size_t)bq * 16 + d] + g_ck[(size_t)bk * 16 + d] + zc;
        }
        float r0[16], r1[16], r2[16];
        for (int i = 0; i < 16; i++) {
            float a = 0.f;
            for (int j = 0; j < 16; j++) a += fmaxf(p[j], 0.f) * W_m1[i * 16 + j];
            r0[i] = a;
        }
        for (int i = 0; i < 16; i++) {
            float a = 0.f;
            for (int j = 0; j < 16; j++) a += fmaxf(r0[j], 0.f) * W_m2[i * 16 + j];
            r1[i] = a;
        }
        for (int i = 0; i < 16; i++) {
            float a = 0.f;
            for (int j = 0; j < 16; j++) a += fmaxf(r1[j], 0.f) * W_m3[i * 16 + j];
            r2[i] = a;
        }
        size_t gidx = ((size_t)b << 19) | ((size_t)kk << 12) | ((size_t)(q & 31) << 7) | hh;
        float* o = out + gidx * 16;
        for (int i = 0; i < 16; i++) o[i] = p[i] + r2[i];
    }
}

// ---------------- launch ----------------
extern "C" void kernel_launch(void* const* d_in, const int* in_sizes, int n_in,
                              void* d_out, int out_size) {
    const float* ref_pos             = (const float*)d_in[0];
    const float* ref_charge          = (const float*)d_in[1];
    const float* atom_pad_mask       = (const float*)d_in[2];
    const float* ref_element         = (const float*)d_in[3];
    const float* ref_atom_name_chars = (const float*)d_in[4];
    const int*   ref_space_uid       = (const int*)  d_in[5];
    const float* atom_to_token       = (const float*)d_in[6];
    const float* s_trunk             = (const float*)d_in[7];
    const float* z                   = (const float*)d_in[8];
    const float* W_feat              = (const float*)d_in[9];
    const float* W_pos               = (const float*)d_in[10];
    const float* W_dist              = (const float*)d_in[11];
    const float* W_maskp             = (const float*)d_in[12];
    const float* ln_s_g              = (const float*)d_in[13];
    const float* ln_s_b              = (const float*)d_in[14];
    const float* W_s2c               = (const float*)d_in[15];
    const float* ln_z_g              = (const float*)d_in[16];
    const float* ln_z_b              = (const float*)d_in[17];
    const float* W_z2p               = (const float*)d_in[18];
    const float* W_cq                = (const float*)d_in[19];
    const float* W_ck                = (const float*)d_in[20];
    const float* W_m1                = (const float*)d_in[21];
    const float* W_m2                = (const float*)d_in[22];
    const float* W_m3                = (const float*)d_in[23];
    float* out = (float*)d_out;

    prep_kernel<<<64, 256>>>(W_feat, W_s2c, W_z2p, ln_z_g, ln_z_b);
    tok_s2c_kernel<<<1536, 256>>>(atom_to_token, s_trunk, ln_s_g, ln_s_b);
    c_kernel<<<(Bc * Nc) / 8, 256>>>(ref_pos, ref_charge, atom_pad_mask,
                                     ref_element, ref_atom_name_chars, W_cq, W_ck);
    z2pc_kernel<<<2 * Bc * Tc, 256>>>(z);
    main_kernel<<<(Bc * 128 * 32 * 128) / 256, 256>>>(ref_pos, atom_pad_mask, ref_space_uid,
                                                      W_pos, W_dist, W_maskp,
                                                      W_m1, W_m2, W_m3, out);
    fixup_kernel<<<Bc * Tc, 128>>>(ref_pos, atom_pad_mask, ref_space_uid, z,
                                   W_pos, W_dist, W_maskp, W_m1, W_m2, W_m3, out);
}

// round 14
// speedup vs baseline: 1.2166x; 1.1116x over previous
#include <cuda_runtime.h>
#include <cstdint>

#define Bc 2
#define Nc 4096
#define Tc 512
#define CAP 32

// ---------------- scratch (static device globals; no allocation) ----------------
__device__ float  g_s2c[Bc * Tc * 128];                 // s_to_c
__device__ int    g_tok[Bc * Nc];                       // token index per atom
__device__ float  g_cq[Bc * Nc * 16];                   // relu(c) @ W_cq.T
__device__ float  g_ck[Bc * Nc * 16];                   // relu(c) @ W_ck.T
__device__ float  g_z2pc[(size_t)Bc * Tc * CAP * 16];   // compact z2p window (2 MB)
__device__ int    g_lo[Bc * Tc];                        // key-token window start per (b,tq)
__device__ int    g_amin[Bc * Tc];
__device__ int    g_amax[Bc * Tc];
__device__ int    g_anyovf;                             // any (b,tq) window exceeded CAP?
__device__ float2 g_WfP2[196 * 128];                    // (w[2f2][ch], w[2f2+1][ch]) non-dup
__device__ float  g_Ws2cT[384 * 128];
__device__ float  g_gw[16 * 128];                       // W_z2p * ln_z_g (folded, f32: fixup)
__device__ float  g_gwh[16 * 128];                      // tf32-high part of g_gw
__device__ float  g_gwl[16 * 128];                      // tf32 residual of g_gw
__device__ float  g_gsum[16];
__device__ float  g_bw[16];

// ---------------- f32x2 / bf16 / tf32 helpers ----------------
__device__ __forceinline__ void fma2(unsigned long long& acc, unsigned long long a, unsigned long long b) {
    asm("fma.rn.f32x2 %0, %1, %2, %0;" : "+l"(acc) : "l"(a), "l"(b));
}
__device__ __forceinline__ unsigned long long dup2(float w) {
    unsigned long long r;
    asm("mov.b64 %0, {%1,%1};" : "=l"(r) : "f"(w));
    return r;
}
__device__ __forceinline__ float lo32(unsigned long long v) { return __uint_as_float((unsigned)(v & 0xffffffffu)); }
__device__ __forceinline__ float hi32(unsigned long long v) { return __uint_as_float((unsigned)(v >> 32)); }
__device__ __forceinline__ unsigned pkbf(float lo, float hi) {
    unsigned r;
    asm("cvt.rn.bf16x2.f32 %0, %1, %2;" : "=r"(r) : "f"(hi), "f"(lo));
    return r;
}
__device__ __forceinline__ unsigned t32(float x) {
    unsigned r;
    asm("cvt.rna.tf32.f32 %0, %1;" : "=r"(r) : "f"(x));
    return r;
}
__device__ __forceinline__ void mma16816(float* d, unsigned a0, unsigned a1, unsigned a2, unsigned a3,
                                         unsigned b0, unsigned b1) {
    asm("mma.sync.aligned.m16n8k16.row.col.f32.bf16.bf16.f32 "
        "{%0,%1,%2,%3}, {%4,%5,%6,%7}, {%8,%9}, {%10,%11,%12,%13};"
        : "=f"(d[0]), "=f"(d[1]), "=f"(d[2]), "=f"(d[3])
        : "r"(a0), "r"(a1), "r"(a2), "r"(a3), "r"(b0), "r"(b1),
          "f"(0.f), "f"(0.f), "f"(0.f), "f"(0.f));
}
__device__ __forceinline__ void mma_tf32(float* d, unsigned a0, unsigned a1, unsigned a2, unsigned a3,
                                         unsigned b0, unsigned b1) {
    asm("mma.sync.aligned.m16n8k8.row.col.f32.tf32.tf32.f32 "
        "{%0,%1,%2,%3}, {%4,%5,%6,%7}, {%8,%9}, {%0,%1,%2,%3};"
        : "+f"(d[0]), "+f"(d[1]), "+f"(d[2]), "+f"(d[3])
        : "r"(a0), "r"(a1), "r"(a2), "r"(a3), "r"(b0), "r"(b1));
}

// ---------------- prep: weight tables + layernorm fold + range/flag init ----------------
__global__ void prep_kernel(const float* __restrict__ W_feat, const float* __restrict__ W_s2c,
                            const float* __restrict__ W_z2p, const float* __restrict__ ln_z_g,
                            const float* __restrict__ ln_z_b) {
    int t = blockIdx.x * blockDim.x + threadIdx.x;
    int nt = gridDim.x * blockDim.x;
    for (int i = t; i < 196 * 128; i += nt) {
        int f2 = i >> 7, ch = i & 127;
        int fi0 = 2 * f2, fi1 = fi0 + 1;
        float w0 = (fi0 < 389) ? W_feat[ch * 389 + fi0] : 0.f;
        float w1 = (fi1 < 389) ? W_feat[ch * 389 + fi1] : 0.f;
        g_WfP2[i] = make_float2(w0, w1);
    }
    for (int i = t; i < 384 * 128; i += nt) {
        int ch = i / 384, f = i % 384;
        g_Ws2cT[f * 128 + ch] = W_s2c[i];
    }
    for (int i = t; i < 16 * 128; i += nt) {
        float w = W_z2p[i] * ln_z_g[i & 127];
        g_gw[i] = w;
        float wh = __uint_as_float(t32(w));
        g_gwh[i] = wh;
        g_gwl[i] = __uint_as_float(t32(w - wh));
    }
    for (int i = t; i < Bc * Tc; i += nt) { g_amin[i] = Nc; g_amax[i] = -1; }
    if (t == 0) g_anyovf = 0;
    if (t < 16) {
        float gs = 0.f, bw = 0.f;
        for (int f = 0; f < 128; f++) {
            gs += W_z2p[t * 128 + f] * ln_z_g[f];
            bw += W_z2p[t * 128 + f] * ln_z_b[f];
        }
        g_gsum[t] = gs;
        g_bw[t] = bw;
    }
}

// ---- fused: blocks [0,1024): token argmax + atom-range; blocks [1024,1536): s2c 2 rows ----
__global__ void __launch_bounds__(256) tok_s2c_kernel(
        const float* __restrict__ a2t, const float* __restrict__ s_trunk,
        const float* __restrict__ g, const float* __restrict__ bta) {
    __shared__ __align__(16) float xs2[2][384];
    __shared__ float red2[2][8];
    int tid = threadIdx.x;

    if (blockIdx.x < 1024) {
        int warp = blockIdx.x * 8 + (tid >> 5);
        int lane = tid & 31;
        const float4* row = (const float4*)(a2t + (size_t)warp * Tc);
        int idx = 0;
#pragma unroll
        for (int i = 0; i < 4; i++) {
            float4 v = row[lane + 32 * i];
            int base = 4 * (lane + 32 * i);
            if (v.x > 0.5f) idx = base;
            if (v.y > 0.5f) idx = base + 1;
            if (v.z > 0.5f) idx = base + 2;
            if (v.w > 0.5f) idx = base + 3;
        }
#pragma unroll
        for (int o = 16; o; o >>= 1) idx = max(idx, __shfl_xor_sync(0xffffffffu, idx, o));
        if (lane == 0) {
            g_tok[warp] = idx;
            int b = warp >> 12;
            int al = warp & (Nc - 1);
            atomicMin(&g_amin[b * Tc + idx], al);
            atomicMax(&g_amax[b * Tc + idx], al);
        }
        return;
    }

    int half = tid >> 7;
    int t2 = tid & 127;
    int row = (blockIdx.x - 1024) * 2 + half;
    const float* x = s_trunk + (size_t)row * 384;
    float v0 = x[t2], v1 = x[t2 + 128], v2 = x[t2 + 256];
    float s = v0 + v1 + v2, s2 = v0 * v0 + v1 * v1 + v2 * v2;
#pragma unroll
    for (int o = 16; o; o >>= 1) {
        s += __shfl_xor_sync(0xffffffffu, s, o);
        s2 += __shfl_xor_sync(0xffffffffu, s2, o);
    }
    if ((t2 & 31) == 0) { red2[half][t2 >> 5] = s; red2[half][4 + (t2 >> 5)] = s2; }
    __syncthreads();
    s = red2[half][0] + red2[half][1] + red2[half][2] + red2[half][3];
    s2 = red2[half][4] + red2[half][5] + red2[half][6] + red2[half][7];
    float mu = s * (1.f / 384.f);
    float var = s2 * (1.f / 384.f) - mu * mu;
    float rs = rsqrtf(var + 1e-5f);
    xs2[half][t2]       = (v0 - mu) * rs * g[t2]       + bta[t2];
    xs2[half][t2 + 128] = (v1 - mu) * rs * g[t2 + 128] + bta[t2 + 128];
    xs2[half][t2 + 256] = (v2 - mu) * rs * g[t2 + 256] + bta[t2 + 256];
    __syncthreads();
    float acc = 0.f;
#pragma unroll 4
    for (int f = 0; f < 384; f++) acc += xs2[half][f] * g_Ws2cT[f * 128 + t2];
    g_s2c[(size_t)row * 128 + t2] = acc;
}

// ---- c embedding + cq/ck heads: 8 atoms/block (grid 1024), LDG.64 weights + reg-dup ----
// (R8/R10-measured winner: 52.5us, occ ~80%)
__global__ void __launch_bounds__(256) c_kernel(
        const float* __restrict__ ref_pos, const float* __restrict__ ref_charge,
        const float* __restrict__ amask, const float* __restrict__ elem,
        const float* __restrict__ chars,
        const float* __restrict__ W_cq, const float* __restrict__ W_ck) {
    __shared__ __align__(16) float sm[5200];
    __shared__ int ts[8];
    int tid = threadIdx.x;
    int abase = blockIdx.x * 8;

#pragma unroll
    for (int pass = 0; pass < 2; pass++) {
        int fi = tid + pass * 256;
        if (fi < 392) {
            float* row = sm + fi * 12;
#pragma unroll 4
            for (int a = 0; a < 8; a++) {
                int atom = abase + a;
                float v;
                if (fi < 3)        v = ref_pos[atom * 3 + fi];
                else if (fi == 3)  v = ref_charge[atom];
                else if (fi == 4)  v = amask[atom];
                else if (fi < 133) v = elem[(size_t)atom * 128 + (fi - 5)];
                else if (fi < 389) v = chars[(size_t)atom * 256 + (fi - 133)];
                else               v = 0.f;
                row[a] = v;
            }
        }
    }
    if (tid < 8) ts[tid] = g_tok[abase + tid];
    __syncthreads();

    int ch = tid & 127;
    int half = tid >> 7;                   // 0: atoms 0..3, 1: atoms 4..7
    const float2* wp = (const float2*)g_WfP2 + ch;
    const char* fb = (const char*)sm + half * 16;
    unsigned long long acc0 = 0, acc1 = 0;
#pragma unroll 8
    for (int f2 = 0; f2 < 196; f2++) {
        float2 ww = wp[(size_t)f2 * 128];
        unsigned long long w0d = dup2(ww.x);
        unsigned long long w1d = dup2(ww.y);
        const char* r0 = fb + (size_t)f2 * 96;
        ulonglong2 fa = *(const ulonglong2*)(r0);
        ulonglong2 fc = *(const ulonglong2*)(r0 + 48);
        fma2(acc0, fa.x, w0d); fma2(acc1, fa.y, w0d);
        fma2(acc0, fc.x, w1d); fma2(acc1, fc.y, w1d);
    }

    int bb = abase >> 12;
    const float* srow = g_s2c + (size_t)bb * Tc * 128 + ch;
    int a0 = half * 4;
    float cv0 = fmaxf(lo32(acc0) + srow[(size_t)ts[a0]     * 128], 0.f);
    float cv1 = fmaxf(hi32(acc0) + srow[(size_t)ts[a0 + 1] * 128], 0.f);
    float cv2 = fmaxf(lo32(acc1) + srow[(size_t)ts[a0 + 2] * 128], 0.f);
    float cv3 = fmaxf(hi32(acc1) + srow[(size_t)ts[a0 + 3] * 128], 0.f);
    __syncthreads();

    float* cs  = sm;                        // [8][128]
    float* wcs = sm + 1024;                 // [2][16][130]
    cs[(a0 + 0) * 128 + ch] = cv0;
    cs[(a0 + 1) * 128 + ch] = cv1;
    cs[(a0 + 2) * 128 + ch] = cv2;
    cs[(a0 + 3) * 128 + ch] = cv3;
    for (int idx = tid; idx < 2 * 16 * 128; idx += 256) {
        int which = idx >> 11, i = (idx >> 7) & 15, chh = idx & 127;
        wcs[(which * 16 + i) * 130 + chh] = which ? W_ck[i * 128 + chh] : W_cq[i * 128 + chh];
    }
    __syncthreads();

    int i = tid & 15, which = (tid >> 4) & 1, a = tid >> 5;
    const unsigned long long* wr = (const unsigned long long*)(wcs + (which * 16 + i) * 130);
    const unsigned long long* cr = (const unsigned long long*)(cs + a * 128);
    unsigned long long s = 0;
#pragma unroll 16
    for (int t2 = 0; t2 < 64; t2++) fma2(s, cr[t2], wr[t2]);
    float* dst = which ? g_ck : g_cq;
    dst[(size_t)(abase + a) * 16 + i] = lo32(s) + hi32(s);
}

// ---- compact z_to_p: 1 block per (b,tq), 32 rows (CAP=32); tf32x3 tensor-core dot ----
__global__ void __launch_bounds__(256) z2pc_kernel(const float* __restrict__ z) {
    __shared__ __align__(16) float xs[32 * 132];
    __shared__ __align__(16) float gwh[16 * 130];
    __shared__ __align__(16) float gwl[16 * 130];
    __shared__ __align__(16) float pd[4 * 32 * 4];
    __shared__ float mus[32], rss[32], gsum_s[16], bw_s[16];
    __shared__ int lo_s;
    int tid = threadIdx.x;
    int bt = blockIdx.x;                 // b*Tc + tq

    if (tid == 0) {
        int lo = 0;
        int amx = g_amax[bt];
        if (amx >= 0) {
            int amn = g_amin[bt];
            int alo = 32 * (amn >> 5) - 48; if (alo < 0) alo = 0;
            int ahi = 32 * (amx >> 5) + 79; if (ahi > Nc - 1) ahi = Nc - 1;
            int bO = (bt >> 9) * Nc;
            lo = g_tok[bO + alo];
            int hi = g_tok[bO + ahi];
            if (hi - lo >= CAP) g_anyovf = 1;
        }
        g_lo[bt] = lo;
        lo_s = lo;
    }
    for (int i = tid; i < 2048; i += 256) {
        int r = (i >> 7) * 130 + (i & 127);
        gwh[r] = g_gwh[i];
        gwl[r] = g_gwl[i];
    }
    if (tid < 16) { gsum_s[tid] = g_gsum[tid]; bw_s[tid] = g_bw[tid]; }
    __syncthreads();
    int lo = lo_s;

    {   // phase 1: load 32 rows (contiguous in z), per-row mean/var; 8 threads/row
        int r = tid >> 3, j = tid & 7;
        int tk = lo + r;
        if (tk > Tc - 1) tk = Tc - 1;
        const float4* src = (const float4*)(z + ((size_t)bt * Tc + tk) * 128) + j * 4;
        float4* dst = (float4*)(xs + r * 132) + j * 4;
        float s = 0.f, s2 = 0.f;
#pragma unroll
        for (int q = 0; q < 4; q++) {
            float4 t = src[q];
            dst[q] = t;
            s += (t.x + t.y) + (t.z + t.w);
            s2 += t.x * t.x + t.y * t.y + t.z * t.z + t.w * t.w;
        }
#pragma unroll
        for (int o = 1; o < 8; o <<= 1) {
            s  += __shfl_xor_sync(0xffffffffu, s, o);
            s2 += __shfl_xor_sync(0xffffffffu, s2, o);
        }
        if (j == 0) {
            float mu = s * (1.f / 128.f);
            float var = s2 * (1.f / 128.f) - mu * mu;
            mus[r] = mu;
            rss[r] = rsqrtf(var + 1e-5f);
        }
    }
    __syncthreads();

    // phase 2: D[32x16] = xs[32x128] * gw^T via m16n8k8 tf32 (tf32x3 for f32 accuracy)
    int lane = tid & 31, wid = tid >> 5;
    int g2 = lane >> 2, t = lane & 3;
    int mn = wid & 3, kh = wid >> 2;      // mn: (m-tile, n-tile); kh: k-half
    int rb = (mn >> 1) * 16;              // row base 0/16
    int cb = (mn & 1) * 8;                // ch base 0/8
    const float* xr0 = xs + (rb + g2) * 132;
    const float* xr1 = xs + (rb + g2 + 8) * 132;
    const unsigned* bhp = (const unsigned*)(gwh + (cb + g2) * 130);
    const unsigned* blp = (const unsigned*)(gwl + (cb + g2) * 130);
    float D[4] = { 0.f, 0.f, 0.f, 0.f };
#pragma unroll
    for (int kc = 0; kc < 8; kc++) {
        int k0 = (kh * 8 + kc) * 8;
        float f0 = xr0[k0 + t],     f1 = xr1[k0 + t];
        float f2 = xr0[k0 + t + 4], f3 = xr1[k0 + t + 4];
        unsigned ah0 = t32(f0), ah1 = t32(f1), ah2 = t32(f2), ah3 = t32(f3);
        unsigned al0 = t32(f0 - __uint_as_float(ah0));
        unsigned al1 = t32(f1 - __uint_as_float(ah1));
        unsigned al2 = t32(f2 - __uint_as_float(ah2));
        unsigned al3 = t32(f3 - __uint_as_float(ah3));
        unsigned bh0 = bhp[k0 + t], bh1 = bhp[k0 + t + 4];
        unsigned bl0 = blp[k0 + t], bl1 = blp[k0 + t + 4];
        mma_tf32(D, ah0, ah1, ah2, ah3, bh0, bh1);
        mma_tf32(D, al0, al1, al2, al3, bh0, bh1);
        mma_tf32(D, ah0, ah1, ah2, ah3, bl0, bl1);
    }
    if (kh == 1) {
        float* p = pd + (mn * 32 + lane) * 4;
        p[0] = D[0]; p[1] = D[1]; p[2] = D[2]; p[3] = D[3];
    }
    __syncthreads();
    if (kh == 0) {
        const float* p = pd + (mn * 32 + lane) * 4;
        D[0] += p[0]; D[1] += p[1]; D[2] += p[2]; D[3] += p[3];
        int lr0 = rb + g2, lr1 = lr0 + 8;
        int c0 = cb + 2 * t, c1 = c0 + 1;
        float* ob = g_z2pc + (size_t)bt * CAP * 16;
        ob[lr0 * 16 + c0] = rss[lr0] * (D[0] - mus[lr0] * gsum_s[c0]) + bw_s[c0];
        ob[lr0 * 16 + c1] = rss[lr0] * (D[1] - mus[lr0] * gsum_s[c1]) + bw_s[c1];
        ob[lr1 * 16 + c0] = rss[lr1] * (D[2] - mus[lr1] * gsum_s[c0]) + bw_s[c0];
        ob[lr1 * 16 + c1] = rss[lr1] * (D[3] - mus[lr1] * gsum_s[c1]) + bw_s[c1];
    }
}

// ---------------- main: 1 position per thread; MLP via warp mma; straight-line ----
__global__ void __launch_bounds__(256) main_kernel(
        const float* __restrict__ ref_pos, const float* __restrict__ amask,
        const int* __restrict__ uid,
        const float* __restrict__ W_pos, const float* __restrict__ W_dist,
        const float* __restrict__ W_maskp,
        const float* __restrict__ W_m1, const float* __restrict__ W_m2,
        const float* __restrict__ W_m3,
        float* __restrict__ out) {
    __shared__ __align__(16) float sw[16 * 8];
    __shared__ unsigned stg[8 * 288];
    __shared__ __align__(16) float res[8 * 640];
    int tid = threadIdx.x;
    int lane = tid & 31, wid = tid >> 5;
    int g = lane >> 2, t = lane & 3;
    if (tid < 16) {
        sw[tid * 8 + 0] = W_pos[3 * tid];
        sw[tid * 8 + 1] = W_pos[3 * tid + 1];
        sw[tid * 8 + 2] = W_pos[3 * tid + 2];
        sw[tid * 8 + 3] = W_dist[tid];
        sw[tid * 8 + 4] = W_maskp[tid];
    }

    unsigned bf[3][4];
#pragma unroll
    for (int L = 0; L < 3; L++) {
        const float* W = (L == 0) ? W_m1 : (L == 1) ? W_m2 : W_m3;
        float2 w00 = *(const float2*)(W + g * 16 + 2 * t);
        float2 w01 = *(const float2*)(W + g * 16 + 2 * t + 8);
        float2 w10 = *(const float2*)(W + (g + 8) * 16 + 2 * t);
        float2 w11 = *(const float2*)(W + (g + 8) * 16 + 2 * t + 8);
        bf[L][0] = pkbf(w00.x, w00.y);
        bf[L][1] = pkbf(w01.x, w01.y);
        bf[L][2] = pkbf(w10.x, w10.y);
        bf[L][3] = pkbf(w11.x, w11.y);
    }
    __syncthreads();

    int gidx = blockIdx.x * 256 + tid;
    int hh = gidx & 127;
    int ww = (gidx >> 7) & 31;
    int kk = (gidx >> 12) & 127;
    int b  = gidx >> 19;
    int q = kk * 32 + ww;
    int bq = b * Nc + q;
    int key = kk * 32 + hh - 48;
    bool inr = (unsigned)key < (unsigned)Nc;
    int bk = b * Nc + (inr ? key : 0);

    float mq = amask[bq];
    float mk = inr ? amask[bk] : 0.f;
    int uq = uid[bq];
    int uk = uid[bk];
    float v = (mq != 0.f && mk != 0.f && uq == uk) ? 1.f : 0.f;

    float qx = ref_pos[bq * 3], qy = ref_pos[bq * 3 + 1], qz = ref_pos[bq * 3 + 2];
    float kx = 0.f, ky = 0.f, kz = 0.f;
    if (inr) { kx = ref_pos[bk * 3]; ky = ref_pos[bk * 3 + 1]; kz = ref_pos[bk * 3 + 2]; }
    float dx = kx - qx, dy = ky - qy, dz = kz - qz;
    float dn = 1.f / (1.f + dx * dx + dy * dy + dz * dz);

    float p[16];
#pragma unroll
    for (int d = 0; d < 16; d++) {
        float4 wv = *(const float4*)(sw + d * 8);
        float e = sw[d * 8 + 4];
        p[d] = v * (dx * wv.x + dy * wv.y + dz * wv.z + dn * wv.w + e);
    }
    {
        const float4* cq4 = (const float4*)(g_cq + (size_t)bq * 16);
#pragma unroll
        for (int i = 0; i < 4; i++) {
            float4 tt = cq4[i];
            p[4 * i] += tt.x; p[4 * i + 1] += tt.y; p[4 * i + 2] += tt.z; p[4 * i + 3] += tt.w;
        }
    }
    if (inr) {
        int tq = g_tok[bq];
        int bt = (b << 9) + tq;
        int lo = g_lo[bt];
        int zoff = bt * CAP;
        int j = g_tok[bk] - lo;
        if (j >= CAP) j = CAP - 1;     // overflow handled exactly by fixup_kernel
        const float4* zp4 = (const float4*)(g_z2pc + (size_t)(zoff + j) * 16);
        const float4* ck4 = (const float4*)(g_ck + (size_t)bk * 16);
#pragma unroll
        for (int i = 0; i < 4; i++) {
            float4 tt = zp4[i], u = ck4[i];
            p[4 * i]     += tt.x + u.x;
            p[4 * i + 1] += tt.y + u.y;
            p[4 * i + 2] += tt.z + u.z;
            p[4 * i + 3] += tt.w + u.w;
        }
    }

    unsigned* h2 = stg + wid * 288;
#pragma unroll
    for (int j2 = 0; j2 < 8; j2++)
        h2[lane * 9 + j2] = pkbf(fmaxf(p[2 * j2], 0.f), fmaxf(p[2 * j2 + 1], 0.f));
    __syncwarp();

    unsigned a0[2], a1[2], a2[2], a3[2];
#pragma unroll
    for (int tt = 0; tt < 2; tt++) {
        int rt = tt * 16;
        a0[tt] = h2[(rt + g) * 9 + t];
        a1[tt] = h2[(rt + g + 8) * 9 + t];
        a2[tt] = h2[(rt + g) * 9 + t + 4];
        a3[tt] = h2[(rt + g + 8) * 9 + t + 4];
    }
    __syncwarp();

    float* wsm = res + wid * 640;
#pragma unroll
    for (int tt = 0; tt < 2; tt++) {
        unsigned u0 = a0[tt], u1 = a1[tt], u2 = a2[tt], u3 = a3[tt];
        float dlo[4], dhi[4];
#pragma unroll
        for (int L = 0; L < 3; L++) {
            mma16816(dlo, u0, u1, u2, u3, bf[L][0], bf[L][1]);
            mma16816(dhi, u0, u1, u2, u3, bf[L][2], bf[L][3]);
            if (L < 2) {
                u0 = pkbf(fmaxf(dlo[0], 0.f), fmaxf(dlo[1], 0.f));
                u1 = pkbf(fmaxf(dlo[2], 0.f), fmaxf(dlo[3], 0.f));
                u2 = pkbf(fmaxf(dhi[0], 0.f), fmaxf(dhi[1], 0.f));
                u3 = pkbf(fmaxf(dhi[2], 0.f), fmaxf(dhi[3], 0.f));
            }
        }
        int r0 = tt * 16 + g, r1 = r0 + 8;
        *(float2*)(wsm + r0 * 20 + 2 * t)     = make_float2(dlo[0], dlo[1]);
        *(float2*)(wsm + r1 * 20 + 2 * t)     = make_float2(dlo[2], dlo[3]);
        *(float2*)(wsm + r0 * 20 + 8 + 2 * t) = make_float2(dhi[0], dhi[1]);
        *(float2*)(wsm + r1 * 20 + 8 + 2 * t) = make_float2(dhi[2], dhi[3]);
    }
    __syncwarp();

    float4* o4 = (float4*)(out + (size_t)gidx * 16);
    const float4* mrow = (const float4*)(wsm + lane * 20);
#pragma unroll
    for (int i = 0; i < 4; i++) {
        float4 mi = mrow[i];
        __stcs(o4 + i, make_float4(p[4 * i] + mi.x, p[4 * i + 1] + mi.y,
                                   p[4 * i + 2] + mi.z, p[4 * i + 3] + mi.w));
    }
}

// ---------------- fixup: exact recompute of window-overflow positions (rare) ----------
__global__ void fixup_kernel(
        const float* __restrict__ ref_pos, const float* __restrict__ amask,
        const int* __restrict__ uid, const float* __restrict__ z,
        const float* __restrict__ W_pos, const float* __restrict__ W_dist,
        const float* __restrict__ W_maskp,
        const float* __restrict__ W_m1, const float* __restrict__ W_m2,
        const float* __restrict__ W_m3,
        float* __restrict__ out) {
    if (!g_anyovf) return;
    int bt = blockIdx.x;
    int amx = g_amax[bt];
    if (amx < 0) return;
    int amn = g_amin[bt];
    int b = bt >> 9;
    int alo = 32 * (amn >> 5) - 48; if (alo < 0) alo = 0;
    int ahi = 32 * (amx >> 5) + 79; if (ahi > Nc - 1) ahi = Nc - 1;
    int lo = g_tok[b * Nc + alo];
    int hi = g_tok[b * Nc + ahi];
    if (hi - lo < CAP) return;

    int hh = threadIdx.x;
    for (int q = amn; q <= amx; q++) {
        int kk = q >> 5;
        int key = kk * 32 + hh - 48;
        if ((unsigned)key >= (unsigned)Nc) continue;
        int bq = b * Nc + q;
        int bk = b * Nc + key;
        int tk2 = g_tok[bk];
        if (tk2 - lo < CAP) continue;

        float mq = amask[bq], mk = amask[bk];
        float vv = (mq != 0.f && mk != 0.f && uid[bq] == uid[bk]) ? 1.f : 0.f;
        float dx = ref_pos[bk * 3] - ref_pos[bq * 3];
        float dy = ref_pos[bk * 3 + 1] - ref_pos[bq * 3 + 1];
        float dz = ref_pos[bk * 3 + 2] - ref_pos[bq * 3 + 2];
        float dn = 1.f / (1.f + dx * dx + dy * dy + dz * dz);

        const float* zrow = z + ((size_t)bt * Tc + tk2) * 128;
        float s = 0.f, s2 = 0.f;
        for (int f = 0; f < 128; f++) { float x = zrow[f]; s += x; s2 += x * x; }
        float mu = s * (1.f / 128.f);
        float rs = rsqrtf(s2 * (1.f / 128.f) - mu * mu + 1e-5f);

        float p[16];
        for (int d = 0; d < 16; d++) {
            float dot = 0.f;
            for (int f = 0; f < 128; f++) dot += zrow[f] * g_gw[d * 128 + f];
            float zc = rs * (dot - mu * g_gsum[d]) + g_bw[d];
            p[d] = vv * (dx * W_pos[3 * d] + dy * W_pos[3 * d + 1] + dz * W_pos[3 * d + 2]
                         + dn * W_dist[d] + W_maskp[d])
                   + g_cq[(size_t)bq * 16 + d] + g_ck[(size_t)bk * 16 + d] + zc;
        }
        float r0[16], r1[16], r2[16];
        for (int i = 0; i < 16; i++) {
            float a = 0.f;
            for (int j = 0; j < 16; j++) a += fmaxf(p[j], 0.f) * W_m1[i * 16 + j];
            r0[i] = a;
        }
        for (int i = 0; i < 16; i++) {
            float a = 0.f;
            for (int j = 0; j < 16; j++) a += fmaxf(r0[j], 0.f) * W_m2[i * 16 + j];
            r1[i] = a;
        }
        for (int i = 0; i < 16; i++) {
            float a = 0.f;
            for (int j = 0; j < 16; j++) a += fmaxf(r1[j], 0.f) * W_m3[i * 16 + j];
            r2[i] = a;
        }
        size_t gidx = ((size_t)b << 19) | ((size_t)kk << 12) | ((size_t)(q & 31) << 7) | hh;
        float* o = out + gidx * 16;
        for (int i = 0; i < 16; i++) o[i] = p[i] + r2[i];
    }
}

// ---------------- launch ----------------
extern "C" void kernel_launch(void* const* d_in, const int* in_sizes, int n_in,
                              void* d_out, int out_size) {
    const float* ref_pos             = (const float*)d_in[0];
    const float* ref_charge          = (const float*)d_in[1];
    const float* atom_pad_mask       = (const float*)d_in[2];
    const float* ref_element         = (const float*)d_in[3];
    const float* ref_atom_name_chars = (const float*)d_in[4];
    const int*   ref_space_uid       = (const int*)  d_in[5];
    const float* atom_to_token       = (const float*)d_in[6];
    const float* s_trunk             = (const float*)d_in[7];
    const float* z                   = (const float*)d_in[8];
    const float* W_feat              = (const float*)d_in[9];
    const float* W_pos               = (const float*)d_in[10];
    const float* W_dist              = (const float*)d_in[11];
    const float* W_maskp             = (const float*)d_in[12];
    const float* ln_s_g              = (const float*)d_in[13];
    const float* ln_s_b              = (const float*)d_in[14];
    const float* W_s2c               = (const float*)d_in[15];
    const float* ln_z_g              = (const float*)d_in[16];
    const float* ln_z_b              = (const float*)d_in[17];
    const float* W_z2p               = (const float*)d_in[18];
    const float* W_cq                = (const float*)d_in[19];
    const float* W_ck                = (const float*)d_in[20];
    const float* W_m1                = (const float*)d_in[21];
    const float* W_m2                = (const float*)d_in[22];
    const float* W_m3                = (const float*)d_in[23];
    float* out = (float*)d_out;

    prep_kernel<<<64, 256>>>(W_feat, W_s2c, W_z2p, ln_z_g, ln_z_b);
    tok_s2c_kernel<<<1536, 256>>>(atom_to_token, s_trunk, ln_s_g, ln_s_b);
    c_kernel<<<(Bc * Nc) / 8, 256>>>(ref_pos, ref_charge, atom_pad_mask,
                                     ref_element, ref_atom_name_chars, W_cq, W_ck);
    z2pc_kernel<<<Bc * Tc, 256>>>(z);
    main_kernel<<<(Bc * 128 * 32 * 128) / 256, 256>>>(ref_pos, atom_pad_mask, ref_space_uid,
                                                      W_pos, W_dist, W_maskp,
                                                      W_m1, W_m2, W_m3, out);
    fixup_kernel<<<Bc * Tc, 128>>>(ref_pos, atom_pad_mask, ref_space_uid, z,
                                   W_pos, W_dist, W_maskp, W_m1, W_m2, W_m3, out);
}

// round 15
// speedup vs baseline: 1.2257x; 1.0075x over previous
#include <cuda_runtime.h>
#include <cstdint>

#define Bc 2
#define Nc 4096
#define Tc 512
#define CAP 32

// ---------------- scratch (static device globals; no allocation) ----------------
__device__ float  g_s2c[Bc * Tc * 128];                 // s_to_c
__device__ int    g_tok[Bc * Nc];                       // token index per atom
__device__ float  g_cq[Bc * Nc * 16];                   // relu(c) @ W_cq.T
__device__ float  g_ck[Bc * Nc * 16];                   // relu(c) @ W_ck.T
__device__ float  g_z2pc[(size_t)Bc * Tc * CAP * 16];   // compact z2p window (2 MB)
__device__ int    g_lo[Bc * Tc];                        // key-token window start per (b,tq)
__device__ int    g_amin[Bc * Tc];
__device__ int    g_amax[Bc * Tc];
__device__ int    g_anyovf;                             // any (b,tq) window exceeded CAP?
__device__ float2 g_WfP2[196 * 128];                    // (w[2f2][ch], w[2f2+1][ch]) non-dup
__device__ float  g_Ws2cT[384 * 128];
__device__ float  g_gw[16 * 128];                       // W_z2p * ln_z_g (folded, f32: fixup)
__device__ float  g_gwh[16 * 128];                      // tf32-high part of g_gw
__device__ float  g_gwl[16 * 128];                      // tf32 residual of g_gw
__device__ float  g_gsum[16];
__device__ float  g_bw[16];

// ---------------- f32x2 / bf16 / tf32 helpers ----------------
__device__ __forceinline__ void fma2(unsigned long long& acc, unsigned long long a, unsigned long long b) {
    asm("fma.rn.f32x2 %0, %1, %2, %0;" : "+l"(acc) : "l"(a), "l"(b));
}
__device__ __forceinline__ unsigned long long dup2(float w) {
    unsigned long long r;
    asm("mov.b64 %0, {%1,%1};" : "=l"(r) : "f"(w));
    return r;
}
__device__ __forceinline__ float lo32(unsigned long long v) { return __uint_as_float((unsigned)(v & 0xffffffffu)); }
__device__ __forceinline__ float hi32(unsigned long long v) { return __uint_as_float((unsigned)(v >> 32)); }
__device__ __forceinline__ unsigned pkbf(float lo, float hi) {
    unsigned r;
    asm("cvt.rn.bf16x2.f32 %0, %1, %2;" : "=r"(r) : "f"(hi), "f"(lo));
    return r;
}
__device__ __forceinline__ unsigned t32(float x) {
    unsigned r;
    asm("cvt.rna.tf32.f32 %0, %1;" : "=r"(r) : "f"(x));
    return r;
}
__device__ __forceinline__ void mma16816(float* d, unsigned a0, unsigned a1, unsigned a2, unsigned a3,
                                         unsigned b0, unsigned b1) {
    asm("mma.sync.aligned.m16n8k16.row.col.f32.bf16.bf16.f32 "
        "{%0,%1,%2,%3}, {%4,%5,%6,%7}, {%8,%9}, {%10,%11,%12,%13};"
        : "=f"(d[0]), "=f"(d[1]), "=f"(d[2]), "=f"(d[3])
        : "r"(a0), "r"(a1), "r"(a2), "r"(a3), "r"(b0), "r"(b1),
          "f"(0.f), "f"(0.f), "f"(0.f), "f"(0.f));
}
__device__ __forceinline__ void mma_tf32(float* d, unsigned a0, unsigned a1, unsigned a2, unsigned a3,
                                         unsigned b0, unsigned b1) {
    asm("mma.sync.aligned.m16n8k8.row.col.f32.tf32.tf32.f32 "
        "{%0,%1,%2,%3}, {%4,%5,%6,%7}, {%8,%9}, {%0,%1,%2,%3};"
        : "+f"(d[0]), "+f"(d[1]), "+f"(d[2]), "+f"(d[3])
        : "r"(a0), "r"(a1), "r"(a2), "r"(a3), "r"(b0), "r"(b1));
}

// ---------------- prep: weight tables + layernorm fold + range/flag init ----------------
__global__ void prep_kernel(const float* __restrict__ W_feat, const float* __restrict__ W_s2c,
                            const float* __restrict__ W_z2p, const float* __restrict__ ln_z_g,
                            const float* __restrict__ ln_z_b) {
    int t = blockIdx.x * blockDim.x + threadIdx.x;
    int nt = gridDim.x * blockDim.x;
    for (int i = t; i < 196 * 128; i += nt) {
        int f2 = i >> 7, ch = i & 127;
        int fi0 = 2 * f2, fi1 = fi0 + 1;
        float w0 = (fi0 < 389) ? W_feat[ch * 389 + fi0] : 0.f;
        float w1 = (fi1 < 389) ? W_feat[ch * 389 + fi1] : 0.f;
        g_WfP2[i] = make_float2(w0, w1);
    }
    for (int i = t; i < 384 * 128; i += nt) {
        int ch = i / 384, f = i % 384;
        g_Ws2cT[f * 128 + ch] = W_s2c[i];
    }
    for (int i = t; i < 16 * 128; i += nt) {
        float w = W_z2p[i] * ln_z_g[i & 127];
        g_gw[i] = w;
        float wh = __uint_as_float(t32(w));
        g_gwh[i] = wh;
        g_gwl[i] = __uint_as_float(t32(w - wh));
    }
    for (int i = t; i < Bc * Tc; i += nt) { g_amin[i] = Nc; g_amax[i] = -1; }
    if (t == 0) g_anyovf = 0;
    if (t < 16) {
        float gs = 0.f, bw = 0.f;
        for (int f = 0; f < 128; f++) {
            gs += W_z2p[t * 128 + f] * ln_z_g[f];
            bw += W_z2p[t * 128 + f] * ln_z_b[f];
        }
        g_gsum[t] = gs;
        g_bw[t] = bw;
    }
}

// ---- fused: blocks [0,1024): token argmax + atom-range; blocks [1024,1536): s2c 2 rows ----
__global__ void __launch_bounds__(256) tok_s2c_kernel(
        const float* __restrict__ a2t, const float* __restrict__ s_trunk,
        const float* __restrict__ g, const float* __restrict__ bta) {
    __shared__ __align__(16) float xs2[2][384];
    __shared__ float red2[2][8];
    int tid = threadIdx.x;

    if (blockIdx.x < 1024) {
        int warp = blockIdx.x * 8 + (tid >> 5);
        int lane = tid & 31;
        const float4* row = (const float4*)(a2t + (size_t)warp * Tc);
        int idx = 0;
#pragma unroll
        for (int i = 0; i < 4; i++) {
            float4 v = row[lane + 32 * i];
            int base = 4 * (lane + 32 * i);
            if (v.x > 0.5f) idx = base;
            if (v.y > 0.5f) idx = base + 1;
            if (v.z > 0.5f) idx = base + 2;
            if (v.w > 0.5f) idx = base + 3;
        }
#pragma unroll
        for (int o = 16; o; o >>= 1) idx = max(idx, __shfl_xor_sync(0xffffffffu, idx, o));
        if (lane == 0) {
            g_tok[warp] = idx;
            int b = warp >> 12;
            int al = warp & (Nc - 1);
            atomicMin(&g_amin[b * Tc + idx], al);
            atomicMax(&g_amax[b * Tc + idx], al);
        }
        return;
    }

    int half = tid >> 7;
    int t2 = tid & 127;
    int row = (blockIdx.x - 1024) * 2 + half;
    const float* x = s_trunk + (size_t)row * 384;
    float v0 = x[t2], v1 = x[t2 + 128], v2 = x[t2 + 256];
    float s = v0 + v1 + v2, s2 = v0 * v0 + v1 * v1 + v2 * v2;
#pragma unroll
    for (int o = 16; o; o >>= 1) {
        s += __shfl_xor_sync(0xffffffffu, s, o);
        s2 += __shfl_xor_sync(0xffffffffu, s2, o);
    }
    if ((t2 & 31) == 0) { red2[half][t2 >> 5] = s; red2[half][4 + (t2 >> 5)] = s2; }
    __syncthreads();
    s = red2[half][0] + red2[half][1] + red2[half][2] + red2[half][3];
    s2 = red2[half][4] + red2[half][5] + red2[half][6] + red2[half][7];
    float mu = s * (1.f / 384.f);
    float var = s2 * (1.f / 384.f) - mu * mu;
    float rs = rsqrtf(var + 1e-5f);
    xs2[half][t2]       = (v0 - mu) * rs * g[t2]       + bta[t2];
    xs2[half][t2 + 128] = (v1 - mu) * rs * g[t2 + 128] + bta[t2 + 128];
    xs2[half][t2 + 256] = (v2 - mu) * rs * g[t2 + 256] + bta[t2 + 256];
    __syncthreads();
    float acc = 0.f;
#pragma unroll 4
    for (int f = 0; f < 384; f++) acc += xs2[half][f] * g_Ws2cT[f * 128 + t2];
    g_s2c[(size_t)row * 128 + t2] = acc;
}

// ==== fused c + z2pc: blocks [0,1024) = c (8 atoms each); [1024,2048) = z2pc per (b,tq) ====
// union smem: c uses [0..5200); z2pc uses xs[0..4224) gwh[4224..6304) gwl[6304..8384)
//             pd[8384..8896) mus[8896..8928) rss[8928..8960) gsum[8960..8976) bw[8976..8992)
__global__ void __launch_bounds__(256) cz_kernel(
        const float* __restrict__ ref_pos, const float* __restrict__ ref_charge,
        const float* __restrict__ amask, const float* __restrict__ elem,
        const float* __restrict__ chars,
        const float* __restrict__ W_cq, const float* __restrict__ W_ck,
        const float* __restrict__ z) {
    __shared__ __align__(16) float sm[8992];
    __shared__ int ts8[8];
    __shared__ int lo_s;
    int tid = threadIdx.x;

    if (blockIdx.x < 1024) {
        // ---------------- c path (byte-identical logic to R14 c_kernel) ----------------
        int abase = blockIdx.x * 8;
#pragma unroll
        for (int pass = 0; pass < 2; pass++) {
            int fi = tid + pass * 256;
            if (fi < 392) {
                float* row = sm + fi * 12;
#pragma unroll 4
                for (int a = 0; a < 8; a++) {
                    int atom = abase + a;
                    float v;
                    if (fi < 3)        v = ref_pos[atom * 3 + fi];
                    else if (fi == 3)  v = ref_charge[atom];
                    else if (fi == 4)  v = amask[atom];
                    else if (fi < 133) v = elem[(size_t)atom * 128 + (fi - 5)];
                    else if (fi < 389) v = chars[(size_t)atom * 256 + (fi - 133)];
                    else               v = 0.f;
                    row[a] = v;
                }
            }
        }
        if (tid < 8) ts8[tid] = g_tok[abase + tid];
        __syncthreads();

        int ch = tid & 127;
        int half = tid >> 7;                   // 0: atoms 0..3, 1: atoms 4..7
        const float2* wp = (const float2*)g_WfP2 + ch;
        const char* fb = (const char*)sm + half * 16;
        unsigned long long acc0 = 0, acc1 = 0;
#pragma unroll 8
        for (int f2 = 0; f2 < 196; f2++) {
            float2 ww = wp[(size_t)f2 * 128];
            unsigned long long w0d = dup2(ww.x);
            unsigned long long w1d = dup2(ww.y);
            const char* r0 = fb + (size_t)f2 * 96;
            ulonglong2 fa = *(const ulonglong2*)(r0);
            ulonglong2 fc = *(const ulonglong2*)(r0 + 48);
            fma2(acc0, fa.x, w0d); fma2(acc1, fa.y, w0d);
            fma2(acc0, fc.x, w1d); fma2(acc1, fc.y, w1d);
        }

        int bb = abase >> 12;
        const float* srow = g_s2c + (size_t)bb * Tc * 128 + ch;
        int a0 = half * 4;
        float cv0 = fmaxf(lo32(acc0) + srow[(size_t)ts8[a0]     * 128], 0.f);
        float cv1 = fmaxf(hi32(acc0) + srow[(size_t)ts8[a0 + 1] * 128], 0.f);
        float cv2 = fmaxf(lo32(acc1) + srow[(size_t)ts8[a0 + 2] * 128], 0.f);
        float cv3 = fmaxf(hi32(acc1) + srow[(size_t)ts8[a0 + 3] * 128], 0.f);
        __syncthreads();

        float* cs  = sm;                        // [8][128]
        float* wcs = sm + 1024;                 // [2][16][130]
        cs[(a0 + 0) * 128 + ch] = cv0;
        cs[(a0 + 1) * 128 + ch] = cv1;
        cs[(a0 + 2) * 128 + ch] = cv2;
        cs[(a0 + 3) * 128 + ch] = cv3;
        for (int idx = tid; idx < 2 * 16 * 128; idx += 256) {
            int which = idx >> 11, i = (idx >> 7) & 15, chh = idx & 127;
            wcs[(which * 16 + i) * 130 + chh] = which ? W_ck[i * 128 + chh] : W_cq[i * 128 + chh];
        }
        __syncthreads();

        int i = tid & 15, which = (tid >> 4) & 1, a = tid >> 5;
        const unsigned long long* wr = (const unsigned long long*)(wcs + (which * 16 + i) * 130);
        const unsigned long long* cr = (const unsigned long long*)(cs + a * 128);
        unsigned long long s = 0;
#pragma unroll 16
        for (int t2 = 0; t2 < 64; t2++) fma2(s, cr[t2], wr[t2]);
        float* dst = which ? g_ck : g_cq;
        dst[(size_t)(abase + a) * 16 + i] = lo32(s) + hi32(s);
        return;
    }

    // ---------------- z2pc path (byte-identical logic to R14 z2pc_kernel) ----------------
    int bt = blockIdx.x - 1024;          // b*Tc + tq
    float* xs  = sm;                      // [32][132]
    float* gwh = sm + 4224;               // [16][130]
    float* gwl = sm + 6304;               // [16][130]
    float* pd  = sm + 8384;               // [4*32*4]
    float* mus = sm + 8896;
    float* rss = sm + 8928;
    float* gsum_s = sm + 8960;
    float* bw_s   = sm + 8976;

    if (tid == 0) {
        int lo = 0;
        int amx = g_amax[bt];
        if (amx >= 0) {
            int amn = g_amin[bt];
            int alo = 32 * (amn >> 5) - 48; if (alo < 0) alo = 0;
            int ahi = 32 * (amx >> 5) + 79; if (ahi > Nc - 1) ahi = Nc - 1;
            int bO = (bt >> 9) * Nc;
            lo = g_tok[bO + alo];
            int hi = g_tok[bO + ahi];
            if (hi - lo >= CAP) g_anyovf = 1;
        }
        g_lo[bt] = lo;
        lo_s = lo;
    }
    for (int i = tid; i < 2048; i += 256) {
        int r = (i >> 7) * 130 + (i & 127);
        gwh[r] = g_gwh[i];
        gwl[r] = g_gwl[i];
    }
    if (tid < 16) { gsum_s[tid] = g_gsum[tid]; bw_s[tid] = g_bw[tid]; }
    __syncthreads();
    int lo = lo_s;

    {   // phase 1: load 32 rows (contiguous in z), per-row mean/var; 8 threads/row
        int r = tid >> 3, j = tid & 7;
        int tk = lo + r;
        if (tk > Tc - 1) tk = Tc - 1;
        const float4* src = (const float4*)(z + ((size_t)bt * Tc + tk) * 128) + j * 4;
        float4* dst = (float4*)(xs + r * 132) + j * 4;
        float s = 0.f, s2 = 0.f;
#pragma unroll
        for (int q = 0; q < 4; q++) {
            float4 t = src[q];
            dst[q] = t;
            s += (t.x + t.y) + (t.z + t.w);
            s2 += t.x * t.x + t.y * t.y + t.z * t.z + t.w * t.w;
        }
#pragma unroll
        for (int o = 1; o < 8; o <<= 1) {
            s  += __shfl_xor_sync(0xffffffffu, s, o);
            s2 += __shfl_xor_sync(0xffffffffu, s2, o);
        }
        if (j == 0) {
            float mu = s * (1.f / 128.f);
            float var = s2 * (1.f / 128.f) - mu * mu;
            mus[r] = mu;
            rss[r] = rsqrtf(var + 1e-5f);
        }
    }
    __syncthreads();

    // phase 2: D[32x16] = xs[32x128] * gw^T via m16n8k8 tf32 (tf32x3 for f32 accuracy)
    int lane = tid & 31, wid = tid >> 5;
    int g2 = lane >> 2, t = lane & 3;
    int mn = wid & 3, kh = wid >> 2;      // mn: (m-tile, n-tile); kh: k-half
    int rb = (mn >> 1) * 16;              // row base 0/16
    int cb = (mn & 1) * 8;                // ch base 0/8
    const float* xr0 = xs + (rb + g2) * 132;
    const float* xr1 = xs + (rb + g2 + 8) * 132;
    const unsigned* bhp = (const unsigned*)(gwh + (cb + g2) * 130);
    const unsigned* blp = (const unsigned*)(gwl + (cb + g2) * 130);
    float D[4] = { 0.f, 0.f, 0.f, 0.f };
#pragma unroll
    for (int kc = 0; kc < 8; kc++) {
        int k0 = (kh * 8 + kc) * 8;
        float f0 = xr0[k0 + t],     f1 = xr1[k0 + t];
        float f2 = xr0[k0 + t + 4], f3 = xr1[k0 + t + 4];
        unsigned ah0 = t32(f0), ah1 = t32(f1), ah2 = t32(f2), ah3 = t32(f3);
        unsigned al0 = t32(f0 - __uint_as_float(ah0));
        unsigned al1 = t32(f1 - __uint_as_float(ah1));
        unsigned al2 = t32(f2 - __uint_as_float(ah2));
        unsigned al3 = t32(f3 - __uint_as_float(ah3));
        unsigned bh0 = bhp[k0 + t], bh1 = bhp[k0 + t + 4];
        unsigned bl0 = blp[k0 + t], bl1 = blp[k0 + t + 4];
        mma_tf32(D, ah0, ah1, ah2, ah3, bh0, bh1);
        mma_tf32(D, al0, al1, al2, al3, bh0, bh1);
        mma_tf32(D, ah0, ah1, ah2, ah3, bl0, bl1);
    }
    if (kh == 1) {
        float* p = pd + (mn * 32 + lane) * 4;
        p[0] = D[0]; p[1] = D[1]; p[2] = D[2]; p[3] = D[3];
    }
    __syncthreads();
    if (kh == 0) {
        const float* p = pd + (mn * 32 + lane) * 4;
        D[0] += p[0]; D[1] += p[1]; D[2] += p[2]; D[3] += p[3];
        int lr0 = rb + g2, lr1 = lr0 + 8;
        int c0 = cb + 2 * t, c1 = c0 + 1;
        float* ob = g_z2pc + (size_t)bt * CAP * 16;
        ob[lr0 * 16 + c0] = rss[lr0] * (D[0] - mus[lr0] * gsum_s[c0]) + bw_s[c0];
        ob[lr0 * 16 + c1] = rss[lr0] * (D[1] - mus[lr0] * gsum_s[c1]) + bw_s[c1];
        ob[lr1 * 16 + c0] = rss[lr1] * (D[2] - mus[lr1] * gsum_s[c0]) + bw_s[c0];
        ob[lr1 * 16 + c1] = rss[lr1] * (D[3] - mus[lr1] * gsum_s[c1]) + bw_s[c1];
    }
}

// ---------------- main: 1 position per thread; MLP via warp mma; straight-line ----
__global__ void __launch_bounds__(256) main_kernel(
        const float* __restrict__ ref_pos, const float* __restrict__ amask,
        const int* __restrict__ uid,
        const float* __restrict__ W_pos, const float* __restrict__ W_dist,
        const float* __restrict__ W_maskp,
        const float* __restrict__ W_m1, const float* __restrict__ W_m2,
        const float* __restrict__ W_m3,
        float* __restrict__ out) {
    __shared__ __align__(16) float sw[16 * 8];
    __shared__ unsigned stg[8 * 288];
    __shared__ __align__(16) float res[8 * 640];
    int tid = threadIdx.x;
    int lane = tid & 31, wid = tid >> 5;
    int g = lane >> 2, t = lane & 3;
    if (tid < 16) {
        sw[tid * 8 + 0] = W_pos[3 * tid];
        sw[tid * 8 + 1] = W_pos[3 * tid + 1];
        sw[tid * 8 + 2] = W_pos[3 * tid + 2];
        sw[tid * 8 + 3] = W_dist[tid];
        sw[tid * 8 + 4] = W_maskp[tid];
    }

    unsigned bf[3][4];
#pragma unroll
    for (int L = 0; L < 3; L++) {
        const float* W = (L == 0) ? W_m1 : (L == 1) ? W_m2 : W_m3;
        float2 w00 = *(const float2*)(W + g * 16 + 2 * t);
        float2 w01 = *(const float2*)(W + g * 16 + 2 * t + 8);
        float2 w10 = *(const float2*)(W + (g + 8) * 16 + 2 * t);
        float2 w11 = *(const float2*)(W + (g + 8) * 16 + 2 * t + 8);
        bf[L][0] = pkbf(w00.x, w00.y);
        bf[L][1] = pkbf(w01.x, w01.y);
        bf[L][2] = pkbf(w10.x, w10.y);
        bf[L][3] = pkbf(w11.x, w11.y);
    }
    __syncthreads();

    int gidx = blockIdx.x * 256 + tid;
    int hh = gidx & 127;
    int ww = (gidx >> 7) & 31;
    int kk = (gidx >> 12) & 127;
    int b  = gidx >> 19;
    int q = kk * 32 + ww;
    int bq = b * Nc + q;
    int key = kk * 32 + hh - 48;
    bool inr = (unsigned)key < (unsigned)Nc;
    int bk = b * Nc + (inr ? key : 0);

    float mq = amask[bq];
    float mk = inr ? amask[bk] : 0.f;
    int uq = uid[bq];
    int uk = uid[bk];
    float v = (mq != 0.f && mk != 0.f && uq == uk) ? 1.f : 0.f;

    float qx = ref_pos[bq * 3], qy = ref_pos[bq * 3 + 1], qz = ref_pos[bq * 3 + 2];
    float kx = 0.f, ky = 0.f, kz = 0.f;
    if (inr) { kx = ref_pos[bk * 3]; ky = ref_pos[bk * 3 + 1]; kz = ref_pos[bk * 3 + 2]; }
    float dx = kx - qx, dy = ky - qy, dz = kz - qz;
    float dn = 1.f / (1.f + dx * dx + dy * dy + dz * dz);

    float p[16];
#pragma unroll
    for (int d = 0; d < 16; d++) {
        float4 wv = *(const float4*)(sw + d * 8);
        float e = sw[d * 8 + 4];
        p[d] = v * (dx * wv.x + dy * wv.y + dz * wv.z + dn * wv.w + e);
    }
    {
        const float4* cq4 = (const float4*)(g_cq + (size_t)bq * 16);
#pragma unroll
        for (int i = 0; i < 4; i++) {
            float4 tt = cq4[i];
            p[4 * i] += tt.x; p[4 * i + 1] += tt.y; p[4 * i + 2] += tt.z; p[4 * i + 3] += tt.w;
        }
    }
    if (inr) {
        int tq = g_tok[bq];
        int bt = (b << 9) + tq;
        int lo = g_lo[bt];
        int zoff = bt * CAP;
        int j = g_tok[bk] - lo;
        if (j >= CAP) j = CAP - 1;     // overflow handled exactly by fixup_kernel
        const float4* zp4 = (const float4*)(g_z2pc + (size_t)(zoff + j) * 16);
        const float4* ck4 = (const float4*)(g_ck + (size_t)bk * 16);
#pragma unroll
        for (int i = 0; i < 4; i++) {
            float4 tt = zp4[i], u = ck4[i];
            p[4 * i]     += tt.x + u.x;
            p[4 * i + 1] += tt.y + u.y;
            p[4 * i + 2] += tt.z + u.z;
            p[4 * i + 3] += tt.w + u.w;
        }
    }

    unsigned* h2 = stg + wid * 288;
#pragma unroll
    for (int j2 = 0; j2 < 8; j2++)
        h2[lane * 9 + j2] = pkbf(fmaxf(p[2 * j2], 0.f), fmaxf(p[2 * j2 + 1], 0.f));
    __syncwarp();

    unsigned a0[2], a1[2], a2[2], a3[2];
#pragma unroll
    for (int tt = 0; tt < 2; tt++) {
        int rt = tt * 16;
        a0[tt] = h2[(rt + g) * 9 + t];
        a1[tt] = h2[(rt + g + 8) * 9 + t];
        a2[tt] = h2[(rt + g) * 9 + t + 4];
        a3[tt] = h2[(rt + g + 8) * 9 + t + 4];
    }
    __syncwarp();

    float* wsm = res + wid * 640;
#pragma unroll
    for (int tt = 0; tt < 2; tt++) {
        unsigned u0 = a0[tt], u1 = a1[tt], u2 = a2[tt], u3 = a3[tt];
        float dlo[4], dhi[4];
#pragma unroll
        for (int L = 0; L < 3; L++) {
            mma16816(dlo, u0, u1, u2, u3, bf[L][0], bf[L][1]);
            mma16816(dhi, u0, u1, u2, u3, bf[L][2], bf[L][3]);
            if (L < 2) {
                u0 = pkbf(fmaxf(dlo[0], 0.f), fmaxf(dlo[1], 0.f));
                u1 = pkbf(fmaxf(dlo[2], 0.f), fmaxf(dlo[3], 0.f));
                u2 = pkbf(fmaxf(dhi[0], 0.f), fmaxf(dhi[1], 0.f));
                u3 = pkbf(fmaxf(dhi[2], 0.f), fmaxf(dhi[3], 0.f));
            }
        }
        int r0 = tt * 16 + g, r1 = r0 + 8;
        *(float2*)(wsm + r0 * 20 + 2 * t)     = make_float2(dlo[0], dlo[1]);
        *(float2*)(wsm + r1 * 20 + 2 * t)     = make_float2(dlo[2], dlo[3]);
        *(float2*)(wsm + r0 * 20 + 8 + 2 * t) = make_float2(dhi[0], dhi[1]);
        *(float2*)(wsm + r1 * 20 + 8 + 2 * t) = make_float2(dhi[2], dhi[3]);
    }
    __syncwarp();

    float4* o4 = (float4*)(out + (size_t)gidx * 16);
    const float4* mrow = (const float4*)(wsm + lane * 20);
#pragma unroll
    for (int i = 0; i < 4; i++) {
        float4 mi = mrow[i];
        __stcs(o4 + i, make_float4(p[4 * i] + mi.x, p[4 * i + 1] + mi.y,
                                   p[4 * i + 2] + mi.z, p[4 * i + 3] + mi.w));
    }
}

// ---------------- fixup: exact recompute of window-overflow positions (rare) ----------
__global__ void fixup_kernel(
        const float* __restrict__ ref_pos, const float* __restrict__ amask,
        const int* __restrict__ uid, const float* __restrict__ z,
        const float* __restrict__ W_pos, const float* __restrict__ W_dist,
        const float* __restrict__ W_maskp,
        const float* __restrict__ W_m1, const float* __restrict__ W_m2,
        const float* __restrict__ W_m3,
        float* __restrict__ out) {
    if (!g_anyovf) return;
    int bt = blockIdx.x;
    int amx = g_amax[bt];
    if (amx < 0) return;
    int amn = g_amin[bt];
    int b = bt >> 9;
    int alo = 32 * (amn >> 5) - 48; if (alo < 0) alo = 0;
    int ahi = 32 * (amx >> 5) + 79; if (ahi > Nc - 1) ahi = Nc - 1;
    int lo = g_tok[b * Nc + alo];
    int hi = g_tok[b * Nc + ahi];
    if (hi - lo < CAP) return;

    int hh = threadIdx.x;
    for (int q = amn; q <= amx; q++) {
        int kk = q >> 5;
        int key = kk * 32 + hh - 48;
        if ((unsigned)key >= (unsigned)Nc) continue;
        int bq = b * Nc + q;
        int bk = b * Nc + key;
        int tk2 = g_tok[bk];
        if (tk2 - lo < CAP) continue;

        float mq = amask[bq], mk = amask[bk];
        float vv = (mq != 0.f && mk != 0.f && uid[bq] == uid[bk]) ? 1.f : 0.f;
        float dx = ref_pos[bk * 3] - ref_pos[bq * 3];
        float dy = ref_pos[bk * 3 + 1] - ref_pos[bq * 3 + 1];
        float dz = ref_pos[bk * 3 + 2] - ref_pos[bq * 3 + 2];
        float dn = 1.f / (1.f + dx * dx + dy * dy + dz * dz);

        const float* zrow = z + ((size_t)bt * Tc + tk2) * 128;
        float s = 0.f, s2 = 0.f;
        for (int f = 0; f < 128; f++) { float x = zrow[f]; s += x; s2 += x * x; }
        float mu = s * (1.f / 128.f);
        float rs = rsqrtf(s2 * (1.f / 128.f) - mu * mu + 1e-5f);

        float p[16];
        for (int d = 0; d < 16; d++) {
            float dot = 0.f;
            for (int f = 0; f < 128; f++) dot += zrow[f] * g_gw[d * 128 + f];
            float zc = rs * (dot - mu * g_gsum[d]) + g_bw[d];
            p[d] = vv * (dx * W_pos[3 * d] + dy * W_pos[3 * d + 1] + dz * W_pos[3 * d + 2]
                         + dn * W_dist[d] + W_maskp[d])
                   + g_cq[(size_t)bq * 16 + d] + g_ck[(size_t)bk * 16 + d] + zc;
        }
        float r0[16], r1[16], r2[16];
        for (int i = 0; i < 16; i++) {
            float a = 0.f;
            for (int j = 0; j < 16; j++) a += fmaxf(p[j], 0.f) * W_m1[i * 16 + j];
            r0[i] = a;
        }
        for (int i = 0; i < 16; i++) {
            float a = 0.f;
            for (int j = 0; j < 16; j++) a += fmaxf(r0[j], 0.f) * W_m2[i * 16 + j];
            r1[i] = a;
        }
        for (int i = 0; i < 16; i++) {
            float a = 0.f;
            for (int j = 0; j < 16; j++) a += fmaxf(r1[j], 0.f) * W_m3[i * 16 + j];
            r2[i] = a;
        }
        size_t gidx = ((size_t)b << 19) | ((size_t)kk << 12) | ((size_t)(q & 31) << 7) | hh;
        float* o = out + gidx * 16;
        for (int i = 0; i < 16; i++) o[i] = p[i] + r2[i];
    }
}

// ---------------- launch ----------------
extern "C" void kernel_launch(void* const* d_in, const int* in_sizes, int n_in,
                              void* d_out, int out_size) {
    const float* ref_pos             = (const float*)d_in[0];
    const float* ref_charge          = (const float*)d_in[1];
    const float* atom_pad_mask       = (const float*)d_in[2];
    const float* ref_element         = (const float*)d_in[3];
    const float* ref_atom_name_chars = (const float*)d_in[4];
    const int*   ref_space_uid       = (const int*)  d_in[5];
    const float* atom_to_token       = (const float*)d_in[6];
    const float* s_trunk             = (const float*)d_in[7];
    const float* z                   = (const float*)d_in[8];
    const float* W_feat              = (const float*)d_in[9];
    const float* W_pos               = (const float*)d_in[10];
    const float* W_dist              = (const float*)d_in[11];
    const float* W_maskp             = (const float*)d_in[12];
    const float* ln_s_g              = (const float*)d_in[13];
    const float* ln_s_b              = (const float*)d_in[14];
    const float* W_s2c               = (const float*)d_in[15];
    const float* ln_z_g              = (const float*)d_in[16];
    const float* ln_z_b              = (const float*)d_in[17];
    const float* W_z2p               = (const float*)d_in[18];
    const float* W_cq                = (const float*)d_in[19];
    const float* W_ck                = (const float*)d_in[20];
    const float* W_m1                = (const float*)d_in[21];
    const float* W_m2                = (const float*)d_in[22];
    const float* W_m3                = (const float*)d_in[23];
    float* out = (float*)d_out;

    prep_kernel<<<64, 256>>>(W_feat, W_s2c, W_z2p, ln_z_g, ln_z_b);
    tok_s2c_kernel<<<1536, 256>>>(atom_to_token, s_trunk, ln_s_g, ln_s_b);
    cz_kernel<<<2048, 256>>>(ref_pos, ref_charge, atom_pad_mask,
                             ref_element, ref_atom_name_chars, W_cq, W_ck, z);
    main_kernel<<<(Bc * 128 * 32 * 128) / 256, 256>>>(ref_pos, atom_pad_mask, ref_space_uid,
                                                      W_pos, W_dist, W_maskp,
                                                      W_m1, W_m2, W_m3, out);
    fixup_kernel<<<Bc * Tc, 128>>>(ref_pos, atom_pad_mask, ref_space_uid, z,
                                   W_pos, W_dist, W_maskp, W_m1, W_m2, W_m3, out);
}

// round 16
// speedup vs baseline: 1.3097x; 1.0685x over previous
#include <cuda_runtime.h>
#include <cstdint>

#define Bc 2
#define Nc 4096
#define Tc 512
#define CAP 32

// ---------------- scratch (static device globals; no allocation) ----------------
__device__ float  g_s2c[Bc * Tc * 128];                 // s_to_c
__device__ int    g_tok[Bc * Nc];                       // token index per atom
__device__ float  g_cq[Bc * Nc * 16];                   // relu(c) @ W_cq.T
__device__ float  g_ck[Bc * Nc * 16];                   // relu(c) @ W_ck.T
__device__ float  g_z2pc[(size_t)Bc * Tc * CAP * 16];   // compact z2p window (2 MB)
__device__ int    g_lo[Bc * Tc];                        // key-token window start per (b,tq)
__device__ int    g_amin[Bc * Tc];
__device__ int    g_amax[Bc * Tc];
__device__ int    g_anyovf;                             // any (b,tq) window exceeded CAP?
__device__ float2 g_WfP2[196 * 128];                    // (w[2f2][ch], w[2f2+1][ch]) non-dup
__device__ float  g_Ws2cT[384 * 128];
__device__ float  g_gw[16 * 128];                       // W_z2p * ln_z_g (folded, f32: fixup)
__device__ float  g_gwh[16 * 128];                      // tf32-high part of g_gw
__device__ float  g_gwl[16 * 128];                      // tf32 residual of g_gw
__device__ float  g_gsum[16];
__device__ float  g_bw[16];

// ---------------- f32x2 / bf16 / tf32 helpers ----------------
__device__ __forceinline__ void fma2(unsigned long long& acc, unsigned long long a, unsigned long long b) {
    asm("fma.rn.f32x2 %0, %1, %2, %0;" : "+l"(acc) : "l"(a), "l"(b));
}
__device__ __forceinline__ unsigned long long dup2(float w) {
    unsigned long long r;
    asm("mov.b64 %0, {%1,%1};" : "=l"(r) : "f"(w));
    return r;
}
__device__ __forceinline__ float lo32(unsigned long long v) { return __uint_as_float((unsigned)(v & 0xffffffffu)); }
__device__ __forceinline__ float hi32(unsigned long long v) { return __uint_as_float((unsigned)(v >> 32)); }
__device__ __forceinline__ unsigned pkbf(float lo, float hi) {
    unsigned r;
    asm("cvt.rn.bf16x2.f32 %0, %1, %2;" : "=r"(r) : "f"(hi), "f"(lo));
    return r;
}
__device__ __forceinline__ unsigned t32(float x) {
    unsigned r;
    asm("cvt.rna.tf32.f32 %0, %1;" : "=r"(r) : "f"(x));
    return r;
}
__device__ __forceinline__ void mma16816(float* d, unsigned a0, unsigned a1, unsigned a2, unsigned a3,
                                         unsigned b0, unsigned b1) {
    asm("mma.sync.aligned.m16n8k16.row.col.f32.bf16.bf16.f32 "
        "{%0,%1,%2,%3}, {%4,%5,%6,%7}, {%8,%9}, {%10,%11,%12,%13};"
        : "=f"(d[0]), "=f"(d[1]), "=f"(d[2]), "=f"(d[3])
        : "r"(a0), "r"(a1), "r"(a2), "r"(a3), "r"(b0), "r"(b1),
          "f"(0.f), "f"(0.f), "f"(0.f), "f"(0.f));
}
__device__ __forceinline__ void mma16816c(float* d, unsigned a0, unsigned a1, unsigned a2, unsigned a3,
                                          unsigned b0, unsigned b1,
                                          float c0, float c1, float c2, float c3) {
    asm("mma.sync.aligned.m16n8k16.row.col.f32.bf16.bf16.f32 "
        "{%0,%1,%2,%3}, {%4,%5,%6,%7}, {%8,%9}, {%10,%11,%12,%13};"
        : "=f"(d[0]), "=f"(d[1]), "=f"(d[2]), "=f"(d[3])
        : "r"(a0), "r"(a1), "r"(a2), "r"(a3), "r"(b0), "r"(b1),
          "f"(c0), "f"(c1), "f"(c2), "f"(c3));
}
__device__ __forceinline__ void mma_tf32(float* d, unsigned a0, unsigned a1, unsigned a2, unsigned a3,
                                         unsigned b0, unsigned b1) {
    asm("mma.sync.aligned.m16n8k8.row.col.f32.tf32.tf32.f32 "
        "{%0,%1,%2,%3}, {%4,%5,%6,%7}, {%8,%9}, {%0,%1,%2,%3};"
        : "+f"(d[0]), "+f"(d[1]), "+f"(d[2]), "+f"(d[3])
        : "r"(a0), "r"(a1), "r"(a2), "r"(a3), "r"(b0), "r"(b1));
}

// ---------------- prep: weight tables + layernorm fold + range/flag init ----------------
__global__ void prep_kernel(const float* __restrict__ W_feat, const float* __restrict__ W_s2c,
                            const float* __restrict__ W_z2p, const float* __restrict__ ln_z_g,
                            const float* __restrict__ ln_z_b) {
    int t = blockIdx.x * blockDim.x + threadIdx.x;
    int nt = gridDim.x * blockDim.x;
    for (int i = t; i < 196 * 128; i += nt) {
        int f2 = i >> 7, ch = i & 127;
        int fi0 = 2 * f2, fi1 = fi0 + 1;
        float w0 = (fi0 < 389) ? W_feat[ch * 389 + fi0] : 0.f;
        float w1 = (fi1 < 389) ? W_feat[ch * 389 + fi1] : 0.f;
        g_WfP2[i] = make_float2(w0, w1);
    }
    for (int i = t; i < 384 * 128; i += nt) {
        int ch = i / 384, f = i % 384;
        g_Ws2cT[f * 128 + ch] = W_s2c[i];
    }
    for (int i = t; i < 16 * 128; i += nt) {
        float w = W_z2p[i] * ln_z_g[i & 127];
        g_gw[i] = w;
        float wh = __uint_as_float(t32(w));
        g_gwh[i] = wh;
        g_gwl[i] = __uint_as_float(t32(w - wh));
    }
    for (int i = t; i < Bc * Tc; i += nt) { g_amin[i] = Nc; g_amax[i] = -1; }
    if (t == 0) g_anyovf = 0;
    if (t < 16) {
        float gs = 0.f, bw = 0.f;
        for (int f = 0; f < 128; f++) {
            gs += W_z2p[t * 128 + f] * ln_z_g[f];
            bw += W_z2p[t * 128 + f] * ln_z_b[f];
        }
        g_gsum[t] = gs;
        g_bw[t] = bw;
    }
}

// ---- fused: blocks [0,1024): token argmax + atom-range; blocks [1024,1536): s2c 2 rows ----
__global__ void __launch_bounds__(256) tok_s2c_kernel(
        const float* __restrict__ a2t, const float* __restrict__ s_trunk,
        const float* __restrict__ g, const float* __restrict__ bta) {
    __shared__ __align__(16) float xs2[2][384];
    __shared__ float red2[2][8];
    int tid = threadIdx.x;

    if (blockIdx.x < 1024) {
        int warp = blockIdx.x * 8 + (tid >> 5);
        int lane = tid & 31;
        const float4* row = (const float4*)(a2t + (size_t)warp * Tc);
        int idx = 0;
#pragma unroll
        for (int i = 0; i < 4; i++) {
            float4 v = row[lane + 32 * i];
            int base = 4 * (lane + 32 * i);
            if (v.x > 0.5f) idx = base;
            if (v.y > 0.5f) idx = base + 1;
            if (v.z > 0.5f) idx = base + 2;
            if (v.w > 0.5f) idx = base + 3;
        }
#pragma unroll
        for (int o = 16; o; o >>= 1) idx = max(idx, __shfl_xor_sync(0xffffffffu, idx, o));
        if (lane == 0) {
            g_tok[warp] = idx;
            int b = warp >> 12;
            int al = warp & (Nc - 1);
            atomicMin(&g_amin[b * Tc + idx], al);
            atomicMax(&g_amax[b * Tc + idx], al);
        }
        return;
    }

    int half = tid >> 7;
    int t2 = tid & 127;
    int row = (blockIdx.x - 1024) * 2 + half;
    const float* x = s_trunk + (size_t)row * 384;
    float v0 = x[t2], v1 = x[t2 + 128], v2 = x[t2 + 256];
    float s = v0 + v1 + v2, s2 = v0 * v0 + v1 * v1 + v2 * v2;
#pragma unroll
    for (int o = 16; o; o >>= 1) {
        s += __shfl_xor_sync(0xffffffffu, s, o);
        s2 += __shfl_xor_sync(0xffffffffu, s2, o);
    }
    if ((t2 & 31) == 0) { red2[half][t2 >> 5] = s; red2[half][4 + (t2 >> 5)] = s2; }
    __syncthreads();
    s = red2[half][0] + red2[half][1] + red2[half][2] + red2[half][3];
    s2 = red2[half][4] + red2[half][5] + red2[half][6] + red2[half][7];
    float mu = s * (1.f / 384.f);
    float var = s2 * (1.f / 384.f) - mu * mu;
    float rs = rsqrtf(var + 1e-5f);
    xs2[half][t2]       = (v0 - mu) * rs * g[t2]       + bta[t2];
    xs2[half][t2 + 128] = (v1 - mu) * rs * g[t2 + 128] + bta[t2 + 128];
    xs2[half][t2 + 256] = (v2 - mu) * rs * g[t2 + 256] + bta[t2 + 256];
    __syncthreads();
    float acc = 0.f;
#pragma unroll 4
    for (int f = 0; f < 384; f++) acc += xs2[half][f] * g_Ws2cT[f * 128 + t2];
    g_s2c[(size_t)row * 128 + t2] = acc;
}

// ==== fused c + z2pc: blocks [0,1024) = c (8 atoms each); [1024,2048) = z2pc per (b,tq) ====
__global__ void __launch_bounds__(256) cz_kernel(
        const float* __restrict__ ref_pos, const float* __restrict__ ref_charge,
        const float* __restrict__ amask, const float* __restrict__ elem,
        const float* __restrict__ chars,
        const float* __restrict__ W_cq, const float* __restrict__ W_ck,
        const float* __restrict__ z) {
    __shared__ __align__(16) float sm[8992];
    __shared__ int ts8[8];
    __shared__ int lo_s;
    int tid = threadIdx.x;

    if (blockIdx.x < 1024) {
        int abase = blockIdx.x * 8;
#pragma unroll
        for (int pass = 0; pass < 2; pass++) {
            int fi = tid + pass * 256;
            if (fi < 392) {
                float* row = sm + fi * 12;
#pragma unroll 4
                for (int a = 0; a < 8; a++) {
                    int atom = abase + a;
                    float v;
                    if (fi < 3)        v = ref_pos[atom * 3 + fi];
                    else if (fi == 3)  v = ref_charge[atom];
                    else if (fi == 4)  v = amask[atom];
                    else if (fi < 133) v = elem[(size_t)atom * 128 + (fi - 5)];
                    else if (fi < 389) v = chars[(size_t)atom * 256 + (fi - 133)];
                    else               v = 0.f;
                    row[a] = v;
                }
            }
        }
        if (tid < 8) ts8[tid] = g_tok[abase + tid];
        __syncthreads();

        int ch = tid & 127;
        int half = tid >> 7;
        const float2* wp = (const float2*)g_WfP2 + ch;
        const char* fb = (const char*)sm + half * 16;
        unsigned long long acc0 = 0, acc1 = 0;
#pragma unroll 8
        for (int f2 = 0; f2 < 196; f2++) {
            float2 ww = wp[(size_t)f2 * 128];
            unsigned long long w0d = dup2(ww.x);
            unsigned long long w1d = dup2(ww.y);
            const char* r0 = fb + (size_t)f2 * 96;
            ulonglong2 fa = *(const ulonglong2*)(r0);
            ulonglong2 fc = *(const ulonglong2*)(r0 + 48);
            fma2(acc0, fa.x, w0d); fma2(acc1, fa.y, w0d);
            fma2(acc0, fc.x, w1d); fma2(acc1, fc.y, w1d);
        }

        int bb = abase >> 12;
        const float* srow = g_s2c + (size_t)bb * Tc * 128 + ch;
        int a0 = half * 4;
        float cv0 = fmaxf(lo32(acc0) + srow[(size_t)ts8[a0]     * 128], 0.f);
        float cv1 = fmaxf(hi32(acc0) + srow[(size_t)ts8[a0 + 1] * 128], 0.f);
        float cv2 = fmaxf(lo32(acc1) + srow[(size_t)ts8[a0 + 2] * 128], 0.f);
        float cv3 = fmaxf(hi32(acc1) + srow[(size_t)ts8[a0 + 3] * 128], 0.f);
        __syncthreads();

        float* cs  = sm;                        // [8][128]
        float* wcs = sm + 1024;                 // [2][16][130]
        cs[(a0 + 0) * 128 + ch] = cv0;
        cs[(a0 + 1) * 128 + ch] = cv1;
        cs[(a0 + 2) * 128 + ch] = cv2;
        cs[(a0 + 3) * 128 + ch] = cv3;
        for (int idx = tid; idx < 2 * 16 * 128; idx += 256) {
            int which = idx >> 11, i = (idx >> 7) & 15, chh = idx & 127;
            wcs[(which * 16 + i) * 130 + chh] = which ? W_ck[i * 128 + chh] : W_cq[i * 128 + chh];
        }
        __syncthreads();

        int i = tid & 15, which = (tid >> 4) & 1, a = tid >> 5;
        const unsigned long long* wr = (const unsigned long long*)(wcs + (which * 16 + i) * 130);
        const unsigned long long* cr = (const unsigned long long*)(cs + a * 128);
        unsigned long long s = 0;
#pragma unroll 16
        for (int t2 = 0; t2 < 64; t2++) fma2(s, cr[t2], wr[t2]);
        float* dst = which ? g_ck : g_cq;
        dst[(size_t)(abase + a) * 16 + i] = lo32(s) + hi32(s);
        return;
    }

    // ---------------- z2pc path ----------------
    int bt = blockIdx.x - 1024;          // b*Tc + tq
    float* xs  = sm;                      // [32][132]
    float* gwh = sm + 4224;               // [16][130]
    float* gwl = sm + 6304;               // [16][130]
    float* pd  = sm + 8384;               // [4*32*4]
    float* mus = sm + 8896;
    float* rss = sm + 8928;
    float* gsum_s = sm + 8960;
    float* bw_s   = sm + 8976;

    if (tid == 0) {
        int lo = 0;
        int amx = g_amax[bt];
        if (amx >= 0) {
            int amn = g_amin[bt];
            int alo = 32 * (amn >> 5) - 48; if (alo < 0) alo = 0;
            int ahi = 32 * (amx >> 5) + 79; if (ahi > Nc - 1) ahi = Nc - 1;
            int bO = (bt >> 9) * Nc;
            lo = g_tok[bO + alo];
            int hi = g_tok[bO + ahi];
            if (hi - lo >= CAP) g_anyovf = 1;
        }
        g_lo[bt] = lo;
        lo_s = lo;
    }
    for (int i = tid; i < 2048; i += 256) {
        int r = (i >> 7) * 130 + (i & 127);
        gwh[r] = g_gwh[i];
        gwl[r] = g_gwl[i];
    }
    if (tid < 16) { gsum_s[tid] = g_gsum[tid]; bw_s[tid] = g_bw[tid]; }
    __syncthreads();
    int lo = lo_s;

    {
        int r = tid >> 3, j = tid & 7;
        int tk = lo + r;
        if (tk > Tc - 1) tk = Tc - 1;
        const float4* src = (const float4*)(z + ((size_t)bt * Tc + tk) * 128) + j * 4;
        float4* dst = (float4*)(xs + r * 132) + j * 4;
        float s = 0.f, s2 = 0.f;
#pragma unroll
        for (int q = 0; q < 4; q++) {
            float4 t = src[q];
            dst[q] = t;
            s += (t.x + t.y) + (t.z + t.w);
            s2 += t.x * t.x + t.y * t.y + t.z * t.z + t.w * t.w;
        }
#pragma unroll
        for (int o = 1; o < 8; o <<= 1) {
            s  += __shfl_xor_sync(0xffffffffu, s, o);
            s2 += __shfl_xor_sync(0xffffffffu, s2, o);
        }
        if (j == 0) {
            float mu = s * (1.f / 128.f);
            float var = s2 * (1.f / 128.f) - mu * mu;
            mus[r] = mu;
            rss[r] = rsqrtf(var + 1e-5f);
        }
    }
    __syncthreads();

    int lane = tid & 31, wid = tid >> 5;
    int g2 = lane >> 2, t = lane & 3;
    int mn = wid & 3, kh = wid >> 2;
    int rb = (mn >> 1) * 16;
    int cb = (mn & 1) * 8;
    const float* xr0 = xs + (rb + g2) * 132;
    const float* xr1 = xs + (rb + g2 + 8) * 132;
    const unsigned* bhp = (const unsigned*)(gwh + (cb + g2) * 130);
    const unsigned* blp = (const unsigned*)(gwl + (cb + g2) * 130);
    float D[4] = { 0.f, 0.f, 0.f, 0.f };
#pragma unroll
    for (int kc = 0; kc < 8; kc++) {
        int k0 = (kh * 8 + kc) * 8;
        float f0 = xr0[k0 + t],     f1 = xr1[k0 + t];
        float f2 = xr0[k0 + t + 4], f3 = xr1[k0 + t + 4];
        unsigned ah0 = t32(f0), ah1 = t32(f1), ah2 = t32(f2), ah3 = t32(f3);
        unsigned al0 = t32(f0 - __uint_as_float(ah0));
        unsigned al1 = t32(f1 - __uint_as_float(ah1));
        unsigned al2 = t32(f2 - __uint_as_float(ah2));
        unsigned al3 = t32(f3 - __uint_as_float(ah3));
        unsigned bh0 = bhp[k0 + t], bh1 = bhp[k0 + t + 4];
        unsigned bl0 = blp[k0 + t], bl1 = blp[k0 + t + 4];
        mma_tf32(D, ah0, ah1, ah2, ah3, bh0, bh1);
        mma_tf32(D, al0, al1, al2, al3, bh0, bh1);
        mma_tf32(D, ah0, ah1, ah2, ah3, bl0, bl1);
    }
    if (kh == 1) {
        float* p = pd + (mn * 32 + lane) * 4;
        p[0] = D[0]; p[1] = D[1]; p[2] = D[2]; p[3] = D[3];
    }
    __syncthreads();
    if (kh == 0) {
        const float* p = pd + (mn * 32 + lane) * 4;
        D[0] += p[0]; D[1] += p[1]; D[2] += p[2]; D[3] += p[3];
        int lr0 = rb + g2, lr1 = lr0 + 8;
        int c0 = cb + 2 * t, c1 = c0 + 1;
        float* ob = g_z2pc + (size_t)bt * CAP * 16;
        ob[lr0 * 16 + c0] = rss[lr0] * (D[0] - mus[lr0] * gsum_s[c0]) + bw_s[c0];
        ob[lr0 * 16 + c1] = rss[lr0] * (D[1] - mus[lr0] * gsum_s[c1]) + bw_s[c1];
        ob[lr1 * 16 + c0] = rss[lr1] * (D[2] - mus[lr1] * gsum_s[c0]) + bw_s[c0];
        ob[lr1 * 16 + c1] = rss[lr1] * (D[3] - mus[lr1] * gsum_s[c1]) + bw_s[c1];
    }
}

// ---- main: 1 position/thread; single f32 p staging; MLP via mma with C=p; direct frag stores ----
__global__ void __launch_bounds__(256) main_kernel(
        const float* __restrict__ ref_pos, const float* __restrict__ amask,
        const int* __restrict__ uid,
        const float* __restrict__ W_pos, const float* __restrict__ W_dist,
        const float* __restrict__ W_maskp,
        const float* __restrict__ W_m1, const float* __restrict__ W_m2,
        const float* __restrict__ W_m3,
        float* __restrict__ out) {
    __shared__ __align__(16) float sw[16 * 8];
    __shared__ __align__(16) float ps[8 * 32 * 18];   // per-warp p staging, stride 18
    int tid = threadIdx.x;
    int lane = tid & 31, wid = tid >> 5;
    int g = lane >> 2, t = lane & 3;
    if (tid < 16) {
        sw[tid * 8 + 0] = W_pos[3 * tid];
        sw[tid * 8 + 1] = W_pos[3 * tid + 1];
        sw[tid * 8 + 2] = W_pos[3 * tid + 2];
        sw[tid * 8 + 3] = W_dist[tid];
        sw[tid * 8 + 4] = W_maskp[tid];
    }

    unsigned bf[3][4];
#pragma unroll
    for (int L = 0; L < 3; L++) {
        const float* W = (L == 0) ? W_m1 : (L == 1) ? W_m2 : W_m3;
        float2 w00 = *(const float2*)(W + g * 16 + 2 * t);
        float2 w01 = *(const float2*)(W + g * 16 + 2 * t + 8);
        float2 w10 = *(const float2*)(W + (g + 8) * 16 + 2 * t);
        float2 w11 = *(const float2*)(W + (g + 8) * 16 + 2 * t + 8);
        bf[L][0] = pkbf(w00.x, w00.y);
        bf[L][1] = pkbf(w01.x, w01.y);
        bf[L][2] = pkbf(w10.x, w10.y);
        bf[L][3] = pkbf(w11.x, w11.y);
    }
    __syncthreads();

    int gidx = blockIdx.x * 256 + tid;
    int hh = gidx & 127;
    int ww = (gidx >> 7) & 31;
    int kk = (gidx >> 12) & 127;
    int b  = gidx >> 19;
    int q = kk * 32 + ww;
    int bq = b * Nc + q;
    int key = kk * 32 + hh - 48;
    bool inr = (unsigned)key < (unsigned)Nc;
    int bk = b * Nc + (inr ? key : 0);

    float mq = amask[bq];
    float mk = inr ? amask[bk] : 0.f;
    int uq = uid[bq];
    int uk = uid[bk];
    float v = (mq != 0.f && mk != 0.f && uq == uk) ? 1.f : 0.f;

    float qx = ref_pos[bq * 3], qy = ref_pos[bq * 3 + 1], qz = ref_pos[bq * 3 + 2];
    float kx = 0.f, ky = 0.f, kz = 0.f;
    if (inr) { kx = ref_pos[bk * 3]; ky = ref_pos[bk * 3 + 1]; kz = ref_pos[bk * 3 + 2]; }
    float dx = kx - qx, dy = ky - qy, dz = kz - qz;
    float dn = 1.f / (1.f + dx * dx + dy * dy + dz * dz);

    float p[16];
#pragma unroll
    for (int d = 0; d < 16; d++) {
        float4 wv = *(const float4*)(sw + d * 8);
        float e = sw[d * 8 + 4];
        p[d] = v * (dx * wv.x + dy * wv.y + dz * wv.z + dn * wv.w + e);
    }
    {
        const float4* cq4 = (const float4*)(g_cq + (size_t)bq * 16);
#pragma unroll
        for (int i = 0; i < 4; i++) {
            float4 tt = cq4[i];
            p[4 * i] += tt.x; p[4 * i + 1] += tt.y; p[4 * i + 2] += tt.z; p[4 * i + 3] += tt.w;
        }
    }
    if (inr) {
        int tq = g_tok[bq];
        int bt = (b << 9) + tq;
        int lo = g_lo[bt];
        int zoff = bt * CAP;
        int j = g_tok[bk] - lo;
        if (j >= CAP) j = CAP - 1;     // overflow handled exactly by fixup_kernel
        const float4* zp4 = (const float4*)(g_z2pc + (size_t)(zoff + j) * 16);
        const float4* ck4 = (const float4*)(g_ck + (size_t)bk * 16);
#pragma unroll
        for (int i = 0; i < 4; i++) {
            float4 tt = zp4[i], u = ck4[i];
            p[4 * i]     += tt.x + u.x;
            p[4 * i + 1] += tt.y + u.y;
            p[4 * i + 2] += tt.z + u.z;
            p[4 * i + 3] += tt.w + u.w;
        }
    }

    // stage p (f32) once: [32 rows x 18 floats] per warp
    float* wps = ps + wid * 576;
#pragma unroll
    for (int j2 = 0; j2 < 8; j2++)
        *(float2*)(wps + lane * 18 + 2 * j2) = make_float2(p[2 * j2], p[2 * j2 + 1]);
    __syncwarp();

    size_t wbase = (size_t)blockIdx.x * 256 + wid * 32;
#pragma unroll
    for (int tt = 0; tt < 2; tt++) {
        int r0 = tt * 16 + g, r1 = r0 + 8;
        float2 clo0 = *(const float2*)(wps + r0 * 18 + 2 * t);       // p[r0][2t,2t+1]
        float2 clo1 = *(const float2*)(wps + r1 * 18 + 2 * t);       // p[r1][2t,2t+1]
        float2 chi0 = *(const float2*)(wps + r0 * 18 + 8 + 2 * t);   // p[r0][8+2t,..]
        float2 chi1 = *(const float2*)(wps + r1 * 18 + 8 + 2 * t);
        unsigned u0 = pkbf(fmaxf(clo0.x, 0.f), fmaxf(clo0.y, 0.f));
        unsigned u1 = pkbf(fmaxf(clo1.x, 0.f), fmaxf(clo1.y, 0.f));
        unsigned u2 = pkbf(fmaxf(chi0.x, 0.f), fmaxf(chi0.y, 0.f));
        unsigned u3 = pkbf(fmaxf(chi1.x, 0.f), fmaxf(chi1.y, 0.f));
        float dlo[4], dhi[4];
#pragma unroll
        for (int L = 0; L < 2; L++) {
            mma16816(dlo, u0, u1, u2, u3, bf[L][0], bf[L][1]);
            mma16816(dhi, u0, u1, u2, u3, bf[L][2], bf[L][3]);
            u0 = pkbf(fmaxf(dlo[0], 0.f), fmaxf(dlo[1], 0.f));
            u1 = pkbf(fmaxf(dlo[2], 0.f), fmaxf(dlo[3], 0.f));
            u2 = pkbf(fmaxf(dhi[0], 0.f), fmaxf(dhi[1], 0.f));
            u3 = pkbf(fmaxf(dhi[2], 0.f), fmaxf(dhi[3], 0.f));
        }
        // last layer accumulates the residual p via the C operand
        mma16816c(dlo, u0, u1, u2, u3, bf[2][0], bf[2][1], clo0.x, clo0.y, clo1.x, clo1.y);
        mma16816c(dhi, u0, u1, u2, u3, bf[2][2], bf[2][3], chi0.x, chi0.y, chi1.x, chi1.y);
        float* o0 = out + (wbase + r0) * 16;
        float* o1 = out + (wbase + r1) * 16;
        __stcs((float2*)(o0 + 2 * t),     make_float2(dlo[0], dlo[1]));
        __stcs((float2*)(o1 + 2 * t),     make_float2(dlo[2], dlo[3]));
        __stcs((float2*)(o0 + 8 + 2 * t), make_float2(dhi[0], dhi[1]));
        __stcs((float2*)(o1 + 8 + 2 * t), make_float2(dhi[2], dhi[3]));
    }
}

// ---------------- fixup: exact recompute of window-overflow positions (rare) ----------
__global__ void fixup_kernel(
        const float* __restrict__ ref_pos, const float* __restrict__ amask,
        const int* __restrict__ uid, const float* __restrict__ z,
        const float* __restrict__ W_pos, const float* __restrict__ W_dist,
        const float* __restrict__ W_maskp,
        const float* __restrict__ W_m1, const float* __restrict__ W_m2,
        const float* __restrict__ W_m3,
        float* __restrict__ out) {
    if (!g_anyovf) return;
    int bt = blockIdx.x;
    int amx = g_amax[bt];
    if (amx < 0) return;
    int amn = g_amin[bt];
    int b = bt >> 9;
    int alo = 32 * (amn >> 5) - 48; if (alo < 0) alo = 0;
    int ahi = 32 * (amx >> 5) + 79; if (ahi > Nc - 1) ahi = Nc - 1;
    int lo = g_tok[b * Nc + alo];
    int hi = g_tok[b * Nc + ahi];
    if (hi - lo < CAP) return;

    int hh = threadIdx.x;
    for (int q = amn; q <= amx; q++) {
        int kk = q >> 5;
        int key = kk * 32 + hh - 48;
        if ((unsigned)key >= (unsigned)Nc) continue;
        int bq = b * Nc + q;
        int bk = b * Nc + key;
        int tk2 = g_tok[bk];
        if (tk2 - lo < CAP) continue;

        float mq = amask[bq], mk = amask[bk];
        float vv = (mq != 0.f && mk != 0.f && uid[bq] == uid[bk]) ? 1.f : 0.f;
        float dx = ref_pos[bk * 3] - ref_pos[bq * 3];
        float dy = ref_pos[bk * 3 + 1] - ref_pos[bq * 3 + 1];
        float dz = ref_pos[bk * 3 + 2] - ref_pos[bq * 3 + 2];
        float dn = 1.f / (1.f + dx * dx + dy * dy + dz * dz);

        const float* zrow = z + ((size_t)bt * Tc + tk2) * 128;
        float s = 0.f, s2 = 0.f;
        for (int f = 0; f < 128; f++) { float x = zrow[f]; s += x; s2 += x * x; }
        float mu = s * (1.f / 128.f);
        float rs = rsqrtf(s2 * (1.f / 128.f) - mu * mu + 1e-5f);

        float p[16];
        for (int d = 0; d < 16; d++) {
            float dot = 0.f;
            for (int f = 0; f < 128; f++) dot += zrow[f] * g_gw[d * 128 + f];
            float zc = rs * (dot - mu * g_gsum[d]) + g_bw[d];
            p[d] = vv * (dx * W_pos[3 * d] + dy * W_pos[3 * d + 1] + dz * W_pos[3 * d + 2]
                         + dn * W_dist[d] + W_maskp[d])
                   + g_cq[(size_t)bq * 16 + d] + g_ck[(size_t)bk * 16 + d] + zc;
        }
        float r0[16], r1[16], r2[16];
        for (int i = 0; i < 16; i++) {
            float a = 0.f;
            for (int j = 0; j < 16; j++) a += fmaxf(p[j], 0.f) * W_m1[i * 16 + j];
            r0[i] = a;
        }
        for (int i = 0; i < 16; i++) {
            float a = 0.f;
            for (int j = 0; j < 16; j++) a += fmaxf(r0[j], 0.f) * W_m2[i * 16 + j];
            r1[i] = a;
        }
        for (int i = 0; i < 16; i++) {
            float a = 0.f;
            for (int j = 0; j < 16; j++) a += fmaxf(r1[j], 0.f) * W_m3[i * 16 + j];
            r2[i] = a;
        }
        size_t gidx = ((size_t)b << 19) | ((size_t)kk << 12) | ((size_t)(q & 31) << 7) | hh;
        float* o = out + gidx * 16;
        for (int i = 0; i < 16; i++) o[i] = p[i] + r2[i];
    }
}

// ---------------- launch ----------------
extern "C" void kernel_launch(void* const* d_in, const int* in_sizes, int n_in,
                              void* d_out, int out_size) {
    const float* ref_pos             = (const float*)d_in[0];
    const float* ref_charge          = (const float*)d_in[1];
    const float* atom_pad_mask       = (const float*)d_in[2];
    const float* ref_element         = (const float*)d_in[3];
    const float* ref_atom_name_chars = (const float*)d_in[4];
    const int*   ref_space_uid       = (const int*)  d_in[5];
    const float* atom_to_token       = (const float*)d_in[6];
    const float* s_trunk             = (const float*)d_in[7];
    const float* z                   = (const float*)d_in[8];
    const float* W_feat              = (const float*)d_in[9];
    const float* W_pos               = (const float*)d_in[10];
    const float* W_dist              = (const float*)d_in[11];
    const float* W_maskp             = (const float*)d_in[12];
    const float* ln_s_g              = (const float*)d_in[13];
    const float* ln_s_b              = (const float*)d_in[14];
    const float* W_s2c               = (const float*)d_in[15];
    const float* ln_z_g              = (const float*)d_in[16];
    const float* ln_z_b              = (const float*)d_in[17];
    const float* W_z2p               = (const float*)d_in[18];
    const float* W_cq                = (const float*)d_in[19];
    const float* W_ck                = (const float*)d_in[20];
    const float* W_m1                = (const float*)d_in[21];
    const float* W_m2                = (const float*)d_in[22];
    const float* W_m3                = (const float*)d_in[23];
    float* out = (float*)d_out;

    prep_kernel<<<64, 256>>>(W_feat, W_s2c, W_z2p, ln_z_g, ln_z_b);
    tok_s2c_kernel<<<1536, 256>>>(atom_to_token, s_trunk, ln_s_g, ln_s_b);
    cz_kernel<<<2048, 256>>>(ref_pos, ref_charge, atom_pad_mask,
                             ref_element, ref_atom_name_chars, W_cq, W_ck, z);
    main_kernel<<<(Bc * 128 * 32 * 128) / 256, 256>>>(ref_pos, atom_pad_mask, ref_space_uid,
                                                      W_pos, W_dist, W_maskp,
                                                      W_m1, W_m2, W_m3, out);
    fixup_kernel<<<Bc * Tc, 128>>>(ref_pos, atom_pad_mask, ref_space_uid, z,
                                   W_pos, W_dist, W_maskp, W_m1, W_m2, W_m3, out);
}